// round 6
// baseline (speedup 1.0000x reference)
#include <cuda_runtime.h>
#include <cuda_bf16.h>
#include <stdint.h>

// Problem dims
#define Bn  8
#define Cc  256
#define ICc 128
#define Nn  4096   // 64*64
#define Mm  1024   // 32*32
#define BN_EPS 1e-5f

// ---------------- scratch (__device__ globals; no allocation) ----------------
__device__ float d_alpha[Cc];
__device__ float d_bias_t[1];
__device__ float d_st[Bn * Nn];
__device__ float d_gT[Bn * Mm * ICc];       // pooled g, (b, m, ic)
__device__ float d_phiT[Bn * Mm * ICc];     // pooled phi, (b, m, ic)
__device__ float d_sp[Bn * Mm];
__device__ float d_ss[Bn * Mm];             // s_p sorted descending
__device__ int   d_perm[Bn * Mm];
__device__ float d_cs1[Bn * 8 * ICc];
__device__ float d_cs2[Bn * 8 * ICc];
__device__ float d_G1[Bn * 1025 * ICc];
__device__ float d_G2[Bn * 1025 * ICc];
__device__ float d_yT[Bn * ICc * Nn];       // y in (b, ic, n) layout (K-major for GEMM2)
__device__ float d_wy[Bn * Cc * Nn];
__device__ float d_bnsum[Cc];
__device__ float d_bnsq[Cc];
__device__ float d_scale[Cc];
__device__ float d_shift[Cc];

// pre-split bf16 weights (hi/lo)
__device__ __align__(16) __nv_bfloat16 d_wgh[ICc * Cc];
__device__ __align__(16) __nv_bfloat16 d_wgl[ICc * Cc];
__device__ __align__(16) __nv_bfloat16 d_wph[ICc * Cc];
__device__ __align__(16) __nv_bfloat16 d_wpl[ICc * Cc];
__device__ __align__(16) __nv_bfloat16 d_wWh[Cc * ICc];
__device__ __align__(16) __nv_bfloat16 d_wWl[Cc * ICc];

// ================= mma.sync helpers (sm_80+ baseline, works on sm_103) =======
__device__ __forceinline__ uint32_t smem_u32(const void* p) {
    uint32_t a;
    asm("{ .reg .u64 t; cvta.to.shared.u64 t, %1; cvt.u32.u64 %0, t; }" : "=r"(a) : "l"(p));
    return a;
}

__device__ __forceinline__ void ldsm4(uint32_t* r, uint32_t addr) {
    asm volatile("ldmatrix.sync.aligned.m8n8.x4.shared.b16 {%0,%1,%2,%3}, [%4];"
                 : "=r"(r[0]), "=r"(r[1]), "=r"(r[2]), "=r"(r[3]) : "r"(addr));
}
__device__ __forceinline__ void ldsm4t(uint32_t* r, uint32_t addr) {
    asm volatile("ldmatrix.sync.aligned.m8n8.x4.trans.shared.b16 {%0,%1,%2,%3}, [%4];"
                 : "=r"(r[0]), "=r"(r[1]), "=r"(r[2]), "=r"(r[3]) : "r"(addr));
}
__device__ __forceinline__ void mma16816(float* d, const uint32_t* a, const uint32_t* b) {
    asm volatile("mma.sync.aligned.m16n8k16.row.col.f32.bf16.bf16.f32 "
                 "{%0,%1,%2,%3},{%4,%5,%6,%7},{%8,%9},{%0,%1,%2,%3};"
                 : "+f"(d[0]), "+f"(d[1]), "+f"(d[2]), "+f"(d[3])
                 : "r"(a[0]), "r"(a[1]), "r"(a[2]), "r"(a[3]), "r"(b[0]), "r"(b[1]));
}

// split fp32 -> (hi,lo) bf16; pack two values into bf16x2 words
__device__ __forceinline__ void pack_split(float a, float b, uint32_t& hp, uint32_t& lp) {
    __nv_bfloat16 ha = __float2bfloat16(a), hb = __float2bfloat16(b);
    __nv_bfloat16 la = __float2bfloat16(a - __bfloat162float(ha));
    __nv_bfloat16 lb = __float2bfloat16(b - __bfloat162float(hb));
    __nv_bfloat162 h2(ha, hb), l2(la, lb);
    hp = *reinterpret_cast<uint32_t*>(&h2);
    lp = *reinterpret_cast<uint32_t*>(&l2);
}

// ---------------- common warp-MMA GEMM mainloop ------------------------------
// acc[16][4] = A[128, K] * B[K, Nn-slice], bf16 hi/lo split (3 MMAs).
// A is PRE-SPLIT bf16 hi/lo, row-major [128][lda].
// B fp32 row-major [K][Nn] (cols n0..n0+127). K chunk = 64.
// Block: 256 thr = 8 warps (2M x 4N), warp tile 64x32.
__device__ __forceinline__ void gemm_mainloop(const __nv_bfloat16* __restrict__ Ahsrc,
                                              const __nv_bfloat16* __restrict__ Alsrc,
                                              int lda,
                                              const float* __restrict__ B,
                                              int nchunks, int n0, char* sm,
                                              float (*acc)[4]) {
    char* Ah = sm;                 // 128 x 64 bf16, 128B rows, swizzled
    char* Al = sm + 16384;
    char* Bh = sm + 32768;         // 64 x 128 bf16, 256B rows, swizzled
    char* Bl = sm + 49152;
    const uint32_t AhB = smem_u32(Ah), AlB = smem_u32(Al);
    const uint32_t BhB = smem_u32(Bh), BlB = smem_u32(Bl);

    const int t = threadIdx.x;
    const int warp = t >> 5, lane = t & 31;
    const int wm = (warp >> 2) * 64;   // warp M offset
    const int wn = (warp & 3) * 32;    // warp N offset

#pragma unroll
    for (int i = 0; i < 16; i++)
#pragma unroll
        for (int j = 0; j < 4; j++) acc[i][j] = 0.f;

    for (int ch = 0; ch < nchunks; ch++) {
        const int k0 = ch * 64;
        // ---- copy A chunk (already bf16 hi/lo): thread -> row r, half h (32 cols)
        {
            int r = t >> 1, h = t & 1;
            const uint2* srcH = reinterpret_cast<const uint2*>(Ahsrc + (size_t)r * lda + k0 + h * 32);
            const uint2* srcL = reinterpret_cast<const uint2*>(Alsrc + (size_t)r * lda + k0 + h * 32);
            uint32_t base = (uint32_t)r * 128 + h * 64;
            uint32_t sw = (uint32_t)(r & 7) << 4;
#pragma unroll
            for (int j = 0; j < 8; j++) {
                uint32_t off = (base + 8u * j) ^ sw;
                *reinterpret_cast<uint2*>(Ah + off) = srcH[j];
                *reinterpret_cast<uint2*>(Al + off) = srcL[j];
            }
        }
        // ---- load + convert B chunk: thread -> k row r, quarter q (32 cols)
        {
            int r = t >> 2, q = t & 3;
            const float* src = B + (size_t)(k0 + r) * Nn + n0 + q * 32;
            uint32_t base = (uint32_t)r * 256 + q * 64;
            uint32_t sw = (uint32_t)(r & 7) << 4;
#pragma unroll
            for (int j = 0; j < 8; j++) {
                float4 v = *reinterpret_cast<const float4*>(src + j * 4);
                uint32_t hp0, lp0, hp1, lp1;
                pack_split(v.x, v.y, hp0, lp0);
                pack_split(v.z, v.w, hp1, lp1);
                uint32_t off = (base + 8u * j) ^ sw;
                *reinterpret_cast<uint2*>(Bh + off) = make_uint2(hp0, hp1);
                *reinterpret_cast<uint2*>(Bl + off) = make_uint2(lp0, lp1);
            }
        }
        __syncthreads();

#pragma unroll
        for (int ks = 0; ks < 4; ks++) {
            uint32_t bh[8], bl[8];
#pragma unroll
            for (int p = 0; p < 2; p++) {
                uint32_t krow = (uint32_t)(ks * 16 + (lane & 15));
                uint32_t off = krow * 256 + (uint32_t)(wn + p * 16) * 2 + ((lane >> 4) << 4);
                off ^= (krow & 7) << 4;
                ldsm4t(bh + p * 4, BhB + off);
                ldsm4t(bl + p * 4, BlB + off);
            }
#pragma unroll
            for (int mi = 0; mi < 4; mi++) {
                uint32_t ah[4], al[4];
                uint32_t row = (uint32_t)(wm + mi * 16 + (lane & 15));
                uint32_t off = row * 128 + (uint32_t)(ks * 32) + ((lane >> 4) << 4);
                off ^= (row & 7) << 4;
                ldsm4(ah, AhB + off);
                ldsm4(al, AlB + off);
#pragma unroll
                for (int ni = 0; ni < 4; ni++) {
                    const uint32_t* fh = &bh[(ni >> 1) * 4 + (ni & 1) * 2];
                    const uint32_t* fl = &bl[(ni >> 1) * 4 + (ni & 1) * 2];
                    float* d = acc[mi * 4 + ni];
                    mma16816(d, ah, fh);
                    mma16816(d, ah, fl);
                    mma16816(d, al, fh);
                }
            }
        }
        __syncthreads();
    }
}

#define GEMM_SMEM 65536

// ---------------- weight pre-split -------------------------------------------
__global__ void k_prep(const float* __restrict__ g_w, const float* __restrict__ phi_w,
                       const float* __restrict__ W_w) {
    int i = blockIdx.x * 256 + threadIdx.x;   // < 32768
    float v = g_w[i];
    __nv_bfloat16 h = __float2bfloat16(v);
    d_wgh[i] = h; d_wgl[i] = __float2bfloat16(v - __bfloat162float(h));
    v = phi_w[i]; h = __float2bfloat16(v);
    d_wph[i] = h; d_wpl[i] = __float2bfloat16(v - __bfloat162float(h));
    v = W_w[i]; h = __float2bfloat16(v);
    d_wWh[i] = h; d_wWl[i] = __float2bfloat16(v - __bfloat162float(h));
}

// GEMM1 + fused 2x2 maxpool + transpose:
// tile covers image rows {2*nt, 2*nt+1}; pooled row ph=nt written to
// (gT|phiT)[(b*Mm + nt*32 + pw)*ICc + o] = max over 2x2 + bias[o].
__global__ __launch_bounds__(256, 2) void k_mma1(const float* __restrict__ x,
                                                 const float* __restrict__ g_b,
                                                 const float* __restrict__ phi_b) {
    extern __shared__ char sm[];
    int nt = blockIdx.x, which = blockIdx.y, b = blockIdx.z;
    float acc[16][4];
    gemm_mainloop(which ? d_wph : d_wgh, which ? d_wpl : d_wgl, Cc,
                  x + (size_t)b * Cc * Nn,
                  4, nt * 128, sm, acc);

    const int t = threadIdx.x;
    const int warp = t >> 5, lane = t & 31;
    const int wm = (warp >> 2) * 64;
    const int wn = (warp & 3) * 32;
    const int rowsel = (wn >= 64) ? 1 : 0;
    const int pwbase = (wn & 63) >> 1;        // 0 or 16

    float* hbuf = reinterpret_cast<float*>(sm);   // [128][66]
#pragma unroll
    for (int mi = 0; mi < 4; mi++) {
        int o0 = wm + mi * 16 + (lane >> 2);
#pragma unroll
        for (int ni = 0; ni < 4; ni++) {
            const float* d = acc[mi * 4 + ni];
            int slot = rowsel * 32 + pwbase + ni * 4 + (lane & 3);
            hbuf[o0 * 66 + slot] = fmaxf(d[0], d[1]);
            hbuf[(o0 + 8) * 66 + slot] = fmaxf(d[2], d[3]);
        }
    }
    __syncthreads();

    const float* bias = which ? phi_b : g_b;
    float* dst = (which ? d_phiT : d_gT) + ((size_t)b * Mm + nt * 32) * ICc;
    int o = (t & 31) * 4;
    float4 bv = *reinterpret_cast<const float4*>(bias + o);
#pragma unroll
    for (int j = 0; j < 4; j++) {
        int pw = (t >> 5) + 8 * j;
        float4 v;
        v.x = fmaxf(hbuf[(o + 0) * 66 + pw], hbuf[(o + 0) * 66 + 32 + pw]) + bv.x;
        v.y = fmaxf(hbuf[(o + 1) * 66 + pw], hbuf[(o + 1) * 66 + 32 + pw]) + bv.y;
        v.z = fmaxf(hbuf[(o + 2) * 66 + pw], hbuf[(o + 2) * 66 + 32 + pw]) + bv.z;
        v.w = fmaxf(hbuf[(o + 3) * 66 + pw], hbuf[(o + 3) * 66 + 32 + pw]) + bv.w;
        *reinterpret_cast<float4*>(dst + (size_t)pw * ICc + o) = v;
    }
}

// GEMM2 + fused BN-stat accumulation:
// d_wy[b][by*128+c][n] = W_w·yT + W_b; per-channel sum/sumsq atomically added.
__global__ __launch_bounds__(256, 2) void k_mma2(const float* __restrict__ W_b) {
    extern __shared__ char sm[];
    int nt = blockIdx.x, by = blockIdx.y, b = blockIdx.z;
    int n0 = nt * 128;
    float acc[16][4];
    gemm_mainloop(d_wWh + (size_t)by * 128 * ICc, d_wWl + (size_t)by * 128 * ICc, ICc,
                  d_yT + (size_t)b * ICc * Nn,
                  2, n0, sm, acc);

    const int t = threadIdx.x;
    const int warp = t >> 5, lane = t & 31;
    const int wm = (warp >> 2) * 64;
    const int wn = (warp & 3) * 32;
    const float* bias = W_b + by * 128;
    float* C = d_wy + (size_t)(b * Cc + by * 128) * Nn;

    float* ssum = reinterpret_cast<float*>(sm);       // [128]
    float* ssq  = ssum + 128;
    if (t < 128) { ssum[t] = 0.f; ssq[t] = 0.f; }
    __syncthreads();

#pragma unroll
    for (int mi = 0; mi < 4; mi++) {
        int o0 = wm + mi * 16 + (lane >> 2);
        float bv0 = bias[o0], bv1 = bias[o0 + 8];
        float s0 = 0.f, q0 = 0.f, s1 = 0.f, q1 = 0.f;
#pragma unroll
        for (int ni = 0; ni < 4; ni++) {
            int col = n0 + wn + ni * 8 + (lane & 3) * 2;
            const float* d = acc[mi * 4 + ni];
            float v0 = d[0] + bv0, v1 = d[1] + bv0;
            float v2 = d[2] + bv1, v3 = d[3] + bv1;
            *reinterpret_cast<float2*>(C + (size_t)o0 * Nn + col) = make_float2(v0, v1);
            *reinterpret_cast<float2*>(C + (size_t)(o0 + 8) * Nn + col) = make_float2(v2, v3);
            s0 += v0 + v1; q0 += v0 * v0 + v1 * v1;
            s1 += v2 + v3; q1 += v2 * v2 + v3 * v3;
        }
#pragma unroll
        for (int off = 1; off < 4; off <<= 1) {
            s0 += __shfl_xor_sync(0xffffffffu, s0, off);
            q0 += __shfl_xor_sync(0xffffffffu, q0, off);
            s1 += __shfl_xor_sync(0xffffffffu, s1, off);
            q1 += __shfl_xor_sync(0xffffffffu, q1, off);
        }
        if ((lane & 3) == 0) {
            atomicAdd(&ssum[o0], s0);
            atomicAdd(&ssq[o0], q0);
            atomicAdd(&ssum[o0 + 8], s1);
            atomicAdd(&ssq[o0 + 8], q1);
        }
    }
    __syncthreads();
    if (t < 128) {
        atomicAdd(&d_bnsum[by * 128 + t], ssum[t]);
        atomicAdd(&d_bnsq[by * 128 + t], ssq[t]);
    }
}

// ---------------- k_alpha: alpha = theta_w^T w_t ; bias_t = w_t . theta_b ----
// also zeroes BN accumulators for this graph replay
__global__ void k_alpha(const float* __restrict__ theta_w,
                        const float* __restrict__ theta_b,
                        const float* __restrict__ cp_w) {
    int c = threadIdx.x;
    d_bnsum[c] = 0.f;
    d_bnsq[c] = 0.f;
    float a = 0.f;
    for (int ic = 0; ic < ICc; ic++) a += cp_w[ic] * theta_w[ic * Cc + c];
    d_alpha[c] = a;
    __shared__ float red[256];
    red[c] = (c < ICc) ? cp_w[c] * theta_b[c] : 0.f;
    __syncthreads();
    for (int s = 128; s > 0; s >>= 1) {
        if (c < s) red[c] += red[c + s];
        __syncthreads();
    }
    if (c == 0) d_bias_t[0] = red[0];
}

// ---------------- k_st: s_t[b][n] = alpha . x[b,:,n] + bias_t ---------------
__global__ void k_st(const float* __restrict__ x) {
    __shared__ float sa[Cc];
    int tid = threadIdx.x;
    sa[tid] = d_alpha[tid];
    __syncthreads();
    int n = blockIdx.x * 256 + tid;
    int b = blockIdx.y;
    const float* xb = x + (size_t)b * Cc * Nn + n;
    float acc = d_bias_t[0];
#pragma unroll 4
    for (int c = 0; c < Cc; c++) acc = fmaf(sa[c], xb[(size_t)c * Nn], acc);
    d_st[b * Nn + n] = acc;
}

// ---------------- s_p[b][m] = w_p . phi_pool[b,:,m] --------------------------
__global__ void k_sp(const float* __restrict__ cp_w) {
    int gw = blockIdx.x * 8 + (threadIdx.x >> 5);
    int lane = threadIdx.x & 31;
    int b = gw >> 10, m = gw & 1023;
    const float* p = d_phiT + ((size_t)b * Mm + m) * ICc;
    const float* wp = cp_w + ICc;
    float s = p[lane] * wp[lane] + p[lane + 32] * wp[lane + 32] +
              p[lane + 64] * wp[lane + 64] + p[lane + 96] * wp[lane + 96];
#pragma unroll
    for (int off = 16; off > 0; off >>= 1) s += __shfl_xor_sync(0xffffffffu, s, off);
    if (lane == 0) d_sp[b * Mm + m] = s;
}

// ---------------- bitonic sort of s_p per batch, descending ------------------
__global__ void k_sort() {
    __shared__ float key[1024];
    __shared__ int   idx[1024];
    int tid = threadIdx.x, b = blockIdx.x;
    key[tid] = d_sp[b * Mm + tid];
    idx[tid] = tid;
    __syncthreads();
    for (int k = 2; k <= 1024; k <<= 1) {
        for (int j = k >> 1; j > 0; j >>= 1) {
            int ixj = tid ^ j;
            if (ixj > tid) {
                bool up = ((tid & k) == 0);
                float a = key[tid], c = key[ixj];
                bool sw = up ? (a < c) : (a > c);
                if (sw) {
                    key[tid] = c; key[ixj] = a;
                    int t = idx[tid]; idx[tid] = idx[ixj]; idx[ixj] = t;
                }
            }
            __syncthreads();
        }
    }
    d_ss[b * Mm + tid] = key[tid];
    d_perm[b * Mm + tid] = idx[tid];
}

// ---------------- prefix tables over sorted order ----------------------------
__global__ void k_p1() {
    __shared__ int   sperm[128];
    __shared__ float sval[128];
    int b = blockIdx.y, ch = blockIdx.x, ic = threadIdx.x;
    sperm[ic] = d_perm[b * Mm + ch * 128 + ic];
    sval[ic]  = d_ss[b * Mm + ch * 128 + ic];
    __syncthreads();
    float s1 = 0.f, s2 = 0.f;
#pragma unroll 4
    for (int j = 0; j < 128; j++) {
        float g = d_gT[((size_t)b * Mm + sperm[j]) * ICc + ic];
        s1 += g;
        s2 = fmaf(sval[j], g, s2);
    }
    d_cs1[((size_t)b * 8 + ch) * ICc + ic] = s1;
    d_cs2[((size_t)b * 8 + ch) * ICc + ic] = s2;
}

__global__ void k_p2() {
    __shared__ int   sperm[128];
    __shared__ float sval[128];
    int b = blockIdx.y, ch = blockIdx.x, ic = threadIdx.x;
    sperm[ic] = d_perm[b * Mm + ch * 128 + ic];
    sval[ic]  = d_ss[b * Mm + ch * 128 + ic];
    __syncthreads();
    float r1 = 0.f, r2 = 0.f;
    for (int cc = 0; cc < ch; cc++) {
        r1 += d_cs1[((size_t)b * 8 + cc) * ICc + ic];
        r2 += d_cs2[((size_t)b * 8 + cc) * ICc + ic];
    }
#pragma unroll 4
    for (int j = 0; j < 128; j++) {
        int kg = ch * 128 + j;
        d_G1[((size_t)b * 1025 + kg) * ICc + ic] = r1;
        d_G2[((size_t)b * 1025 + kg) * ICc + ic] = r2;
        float g = d_gT[((size_t)b * Mm + sperm[j]) * ICc + ic];
        r1 += g;
        r2 = fmaf(sval[j], g, r2);
    }
    if (ch == 7) {
        d_G1[((size_t)b * 1025 + 1024) * ICc + ic] = r1;
        d_G2[((size_t)b * 1025 + 1024) * ICc + ic] = r2;
    }
}

// ---------------- y: yT[b][ic][n] = (s_t[n]*G1[k(n),ic] + G2[k(n),ic]) / M ---
__global__ __launch_bounds__(256) void k_y() {
    extern __shared__ float tile[];          // [128][129]
    __shared__ int   s_lo[128];
    __shared__ float s_st[128];
    int t = threadIdx.x;
    int b = blockIdx.y, n0 = blockIdx.x * 128;

    if (t < 128) {
        float st = d_st[b * Nn + n0 + t];
        float tgt = -st;
        const float* ss = d_ss + b * Mm;
        int lo = 0, hi = 1024;
        while (lo < hi) {
            int mid = (lo + hi) >> 1;
            if (ss[mid] > tgt) lo = mid + 1; else hi = mid;
        }
        s_lo[t] = lo;
        s_st[t] = st;
    }
    __syncthreads();

    int ic = t & 127, nh = t >> 7;
    for (int j = 0; j < 64; j++) {
        int nl = nh * 64 + j;
        int lo = s_lo[nl];
        float st = s_st[nl];
        size_t gidx = ((size_t)b * 1025 + lo) * ICc + ic;
        tile[nl * 129 + ic] = (st * d_G1[gidx] + d_G2[gidx]) * (1.0f / 1024.0f);
    }
    __syncthreads();

    int nl = t & 127, half = t >> 7;
    for (int j = 0; j < 64; j++) {
        int ico = half * 64 + j;
        d_yT[((size_t)b * ICc + ico) * Nn + n0 + nl] = tile[nl * 129 + ico];
    }
}

// ---------------- BN stats -> scale/shift ------------------------------------
__global__ void k_bnstats(const float* __restrict__ gamma, const float* __restrict__ beta) {
    int c = threadIdx.x;
    const float inv_cnt = 1.0f / (Bn * Nn);
    float mean = d_bnsum[c] * inv_cnt;
    float var = d_bnsq[c] * inv_cnt - mean * mean;
    float scale = rsqrtf(var + BN_EPS) * gamma[c];
    d_scale[c] = scale;
    d_shift[c] = beta[c] - mean * scale;
}

// ---------------- final: out = wy*scale + shift + x --------------------------
__global__ void k_final(const float* __restrict__ x, float* __restrict__ out) {
    size_t i = ((size_t)blockIdx.x * 256 + threadIdx.x) * 4;
    int c = (int)((i / Nn) % Cc);
    float4 wv = *reinterpret_cast<const float4*>(d_wy + i);
    float4 xv = *reinterpret_cast<const float4*>(x + i);
    float sc = d_scale[c], sh = d_shift[c];
    float4 o;
    o.x = fmaf(wv.x, sc, sh) + xv.x;
    o.y = fmaf(wv.y, sc, sh) + xv.y;
    o.z = fmaf(wv.z, sc, sh) + xv.z;
    o.w = fmaf(wv.w, sc, sh) + xv.w;
    *reinterpret_cast<float4*>(out + i) = o;
}

// ---------------- launch -----------------------------------------------------
extern "C" void kernel_launch(void* const* d_in, const int* in_sizes, int n_in,
                              void* d_out, int out_size) {
    const float* x       = (const float*)d_in[0];
    const float* g_w     = (const float*)d_in[1];
    const float* g_b     = (const float*)d_in[2];
    const float* theta_w = (const float*)d_in[3];
    const float* theta_b = (const float*)d_in[4];
    const float* phi_w   = (const float*)d_in[5];
    const float* phi_b   = (const float*)d_in[6];
    const float* cp_w    = (const float*)d_in[7];
    const float* W_w     = (const float*)d_in[8];
    const float* W_b     = (const float*)d_in[9];
    const float* bn_g    = (const float*)d_in[10];
    const float* bn_b    = (const float*)d_in[11];
    float* out = (float*)d_out;

    static bool attr_done = false;
    if (!attr_done) {
        cudaFuncSetAttribute(k_mma1, cudaFuncAttributeMaxDynamicSharedMemorySize, GEMM_SMEM);
        cudaFuncSetAttribute(k_mma2, cudaFuncAttributeMaxDynamicSharedMemorySize, GEMM_SMEM);
        cudaFuncSetAttribute(k_y, cudaFuncAttributeMaxDynamicSharedMemorySize, 128 * 129 * 4);
        attr_done = true;
    }

    k_alpha<<<1, 256>>>(theta_w, theta_b, cp_w);
    k_prep<<<128, 256>>>(g_w, phi_w, W_w);
    k_mma1<<<dim3(32, 2, Bn), 256, GEMM_SMEM>>>(x, g_b, phi_b);
    k_st<<<dim3(Nn / 256, Bn), 256>>>(x);
    k_sp<<<(Bn * Mm) / 8, 256>>>(cp_w);
    k_sort<<<Bn, 1024>>>();
    k_p1<<<dim3(8, Bn), 128>>>();
    k_p2<<<dim3(8, Bn), 128>>>();
    k_y<<<dim3(32, Bn), 256, 128 * 129 * 4>>>();
    k_mma2<<<dim3(32, 2, Bn), 256, GEMM_SMEM>>>(W_b);
    k_bnstats<<<1, 256>>>(bn_g, bn_b);
    k_final<<<(Bn * Cc * Nn) / (256 * 4), 256>>>(x, out);
}

// round 7
// speedup vs baseline: 1.3759x; 1.3759x over previous
#include <cuda_runtime.h>
#include <cuda_bf16.h>
#include <stdint.h>

// Problem dims
#define Bn  8
#define Cc  256
#define ICc 128
#define Nn  4096   // 64*64
#define Mm  1024   // 32*32
#define BN_EPS 1e-5f

// ---------------- scratch (__device__ globals; no allocation) ----------------
__device__ float d_alpha[Cc];
__device__ float d_bias_t[1];
__device__ float d_gp[Bn * 2 * ICc * Nn];   // g (o<128) + phi (o>=128) conv outputs
__device__ float d_st[Bn * Nn];
__device__ float d_gT[Bn * Mm * ICc];       // pooled g, (b, m, ic)
__device__ float d_phiT[Bn * Mm * ICc];     // pooled phi, (b, m, ic)
__device__ float d_sp[Bn * Mm];
__device__ float d_ss[Bn * Mm];             // s_p sorted descending
__device__ int   d_perm[Bn * Mm];
__device__ float d_cs1[Bn * 8 * ICc];
__device__ float d_cs2[Bn * 8 * ICc];
__device__ float d_G1[Bn * 1025 * ICc];
__device__ float d_G2[Bn * 1025 * ICc];
__device__ float d_yT[Bn * ICc * Nn];       // y in (b, ic, n) layout (K-major for GEMM2)
__device__ float d_wy[Bn * Cc * Nn];
__device__ float d_scale[Cc];
__device__ float d_shift[Cc];

// pre-split bf16 weights (hi/lo)
__device__ __align__(16) __nv_bfloat16 d_wgh[ICc * Cc];
__device__ __align__(16) __nv_bfloat16 d_wgl[ICc * Cc];
__device__ __align__(16) __nv_bfloat16 d_wph[ICc * Cc];
__device__ __align__(16) __nv_bfloat16 d_wpl[ICc * Cc];
__device__ __align__(16) __nv_bfloat16 d_wWh[Cc * ICc];
__device__ __align__(16) __nv_bfloat16 d_wWl[Cc * ICc];

// ================= mma.sync helpers (sm_80+ baseline, works on sm_103) =======
__device__ __forceinline__ uint32_t smem_u32(const void* p) {
    uint32_t a;
    asm("{ .reg .u64 t; cvta.to.shared.u64 t, %1; cvt.u32.u64 %0, t; }" : "=r"(a) : "l"(p));
    return a;
}

__device__ __forceinline__ void ldsm4(uint32_t* r, uint32_t addr) {
    asm volatile("ldmatrix.sync.aligned.m8n8.x4.shared.b16 {%0,%1,%2,%3}, [%4];"
                 : "=r"(r[0]), "=r"(r[1]), "=r"(r[2]), "=r"(r[3]) : "r"(addr));
}
__device__ __forceinline__ void ldsm4t(uint32_t* r, uint32_t addr) {
    asm volatile("ldmatrix.sync.aligned.m8n8.x4.trans.shared.b16 {%0,%1,%2,%3}, [%4];"
                 : "=r"(r[0]), "=r"(r[1]), "=r"(r[2]), "=r"(r[3]) : "r"(addr));
}
__device__ __forceinline__ void mma16816(float* d, const uint32_t* a, const uint32_t* b) {
    asm volatile("mma.sync.aligned.m16n8k16.row.col.f32.bf16.bf16.f32 "
                 "{%0,%1,%2,%3},{%4,%5,%6,%7},{%8,%9},{%0,%1,%2,%3};"
                 : "+f"(d[0]), "+f"(d[1]), "+f"(d[2]), "+f"(d[3])
                 : "r"(a[0]), "r"(a[1]), "r"(a[2]), "r"(a[3]), "r"(b[0]), "r"(b[1]));
}

// split fp32 -> (hi,lo) bf16; pack two values into bf16x2 words
__device__ __forceinline__ void pack_split(float a, float b, uint32_t& hp, uint32_t& lp) {
    __nv_bfloat16 ha = __float2bfloat16(a), hb = __float2bfloat16(b);
    __nv_bfloat16 la = __float2bfloat16(a - __bfloat162float(ha));
    __nv_bfloat16 lb = __float2bfloat16(b - __bfloat162float(hb));
    __nv_bfloat162 h2(ha, hb), l2(la, lb);
    hp = *reinterpret_cast<uint32_t*>(&h2);
    lp = *reinterpret_cast<uint32_t*>(&l2);
}

// ---------------- common warp-MMA GEMM core ----------------------------------
// C[128, Nn-slice] = A[128, K] * B[K, Nn-slice] + bias; A pre-split bf16 hi/lo.
// Block: 256 thr = 8 warps (2M x 4N), warp tile 64x32. K chunk = 64.
__device__ __forceinline__ void gemm_core(const __nv_bfloat16* __restrict__ Ahsrc,
                                          const __nv_bfloat16* __restrict__ Alsrc,
                                          int lda,
                                          const float* __restrict__ bias,
                                          const float* __restrict__ B,
                                          float* __restrict__ C,
                                          int nchunks, int n0, char* sm) {
    char* Ah = sm;                 // 128 x 64 bf16, 128B rows, swizzled
    char* Al = sm + 16384;
    char* Bh = sm + 32768;         // 64 x 128 bf16, 256B rows, swizzled
    char* Bl = sm + 49152;
    const uint32_t AhB = smem_u32(Ah), AlB = smem_u32(Al);
    const uint32_t BhB = smem_u32(Bh), BlB = smem_u32(Bl);

    const int t = threadIdx.x;
    const int warp = t >> 5, lane = t & 31;
    const int wm = (warp >> 2) * 64;   // warp M offset
    const int wn = (warp & 3) * 32;    // warp N offset

    float acc[16][4];
#pragma unroll
    for (int i = 0; i < 16; i++)
#pragma unroll
        for (int j = 0; j < 4; j++) acc[i][j] = 0.f;

    for (int ch = 0; ch < nchunks; ch++) {
        const int k0 = ch * 64;
        // ---- copy A chunk (already bf16 hi/lo): thread -> row r, half h (32 cols)
        {
            int r = t >> 1, h = t & 1;
            const uint2* srcH = reinterpret_cast<const uint2*>(Ahsrc + (size_t)r * lda + k0 + h * 32);
            const uint2* srcL = reinterpret_cast<const uint2*>(Alsrc + (size_t)r * lda + k0 + h * 32);
            uint32_t base = (uint32_t)r * 128 + h * 64;
            uint32_t sw = (uint32_t)(r & 7) << 4;
#pragma unroll
            for (int j = 0; j < 8; j++) {
                uint32_t off = (base + 8u * j) ^ sw;
                *reinterpret_cast<uint2*>(Ah + off) = srcH[j];
                *reinterpret_cast<uint2*>(Al + off) = srcL[j];
            }
        }
        // ---- load + convert B chunk: thread -> k row r, quarter q (32 cols)
        {
            int r = t >> 2, q = t & 3;
            const float* src = B + (size_t)(k0 + r) * Nn + n0 + q * 32;
            uint32_t base = (uint32_t)r * 256 + q * 64;
            uint32_t sw = (uint32_t)(r & 7) << 4;
#pragma unroll
            for (int j = 0; j < 8; j++) {
                float4 v = *reinterpret_cast<const float4*>(src + j * 4);
                uint32_t hp0, lp0, hp1, lp1;
                pack_split(v.x, v.y, hp0, lp0);
                pack_split(v.z, v.w, hp1, lp1);
                uint32_t off = (base + 8u * j) ^ sw;
                *reinterpret_cast<uint2*>(Bh + off) = make_uint2(hp0, hp1);
                *reinterpret_cast<uint2*>(Bl + off) = make_uint2(lp0, lp1);
            }
        }
        __syncthreads();

#pragma unroll
        for (int ks = 0; ks < 4; ks++) {
            uint32_t bh[8], bl[8];
#pragma unroll
            for (int p = 0; p < 2; p++) {
                uint32_t krow = (uint32_t)(ks * 16 + (lane & 15));
                uint32_t off = krow * 256 + (uint32_t)(wn + p * 16) * 2 + ((lane >> 4) << 4);
                off ^= (krow & 7) << 4;
                ldsm4t(bh + p * 4, BhB + off);
                ldsm4t(bl + p * 4, BlB + off);
            }
#pragma unroll
            for (int mi = 0; mi < 4; mi++) {
                uint32_t ah[4], al[4];
                uint32_t row = (uint32_t)(wm + mi * 16 + (lane & 15));
                uint32_t off = row * 128 + (uint32_t)(ks * 32) + ((lane >> 4) << 4);
                off ^= (row & 7) << 4;
                ldsm4(ah, AhB + off);
                ldsm4(al, AlB + off);
#pragma unroll
                for (int ni = 0; ni < 4; ni++) {
                    const uint32_t* fh = &bh[(ni >> 1) * 4 + (ni & 1) * 2];
                    const uint32_t* fl = &bl[(ni >> 1) * 4 + (ni & 1) * 2];
                    float* d = acc[mi * 4 + ni];
                    mma16816(d, ah, fh);
                    mma16816(d, ah, fl);
                    mma16816(d, al, fh);
                }
            }
        }
        __syncthreads();
    }

    // ---- epilogue: bias + store fp32
#pragma unroll
    for (int mi = 0; mi < 4; mi++) {
        int o0 = wm + mi * 16 + (lane >> 2);
        float bv0 = bias[o0], bv1 = bias[o0 + 8];
#pragma unroll
        for (int ni = 0; ni < 4; ni++) {
            int col = n0 + wn + ni * 8 + (lane & 3) * 2;
            const float* d = acc[mi * 4 + ni];
            float2 v0 = make_float2(d[0] + bv0, d[1] + bv0);
            float2 v1 = make_float2(d[2] + bv1, d[3] + bv1);
            *reinterpret_cast<float2*>(C + (size_t)o0 * Nn + col) = v0;
            *reinterpret_cast<float2*>(C + (size_t)(o0 + 8) * Nn + col) = v1;
        }
    }
}

#define GEMM_SMEM 65536

// ---------------- weight pre-split -------------------------------------------
__global__ void k_prep(const float* __restrict__ g_w, const float* __restrict__ phi_w,
                       const float* __restrict__ W_w) {
    int i = blockIdx.x * 256 + threadIdx.x;   // < 32768
    float v = g_w[i];
    __nv_bfloat16 h = __float2bfloat16(v);
    d_wgh[i] = h; d_wgl[i] = __float2bfloat16(v - __bfloat162float(h));
    v = phi_w[i]; h = __float2bfloat16(v);
    d_wph[i] = h; d_wpl[i] = __float2bfloat16(v - __bfloat162float(h));
    v = W_w[i]; h = __float2bfloat16(v);
    d_wWh[i] = h; d_wWl[i] = __float2bfloat16(v - __bfloat162float(h));
}

// GEMM1: d_gp[b][which*128+o][n] = (g_w|phi_w)[o,:]·x[b,:,n] + bias[o]; K=256
__global__ __launch_bounds__(256) void k_mma1(const float* __restrict__ x,
                                              const float* __restrict__ g_b,
                                              const float* __restrict__ phi_b) {
    extern __shared__ char sm[];
    int which = blockIdx.y, b = blockIdx.z;
    gemm_core(which ? d_wph : d_wgh, which ? d_wpl : d_wgl, Cc,
              which ? phi_b : g_b,
              x + (size_t)b * Cc * Nn,
              d_gp + (size_t)(b * 2 + which) * ICc * Nn,
              4, blockIdx.x * 128, sm);
}

// GEMM2: d_wy[b][by*128+c][n] = W_w[by*128+c,:]·yT[b,:,n] + W_b; K=128
__global__ __launch_bounds__(256) void k_mma2(const float* __restrict__ W_b) {
    extern __shared__ char sm[];
    int by = blockIdx.y, b = blockIdx.z;
    gemm_core(d_wWh + (size_t)by * 128 * ICc, d_wWl + (size_t)by * 128 * ICc, ICc,
              W_b + by * 128,
              d_yT + (size_t)b * ICc * Nn,
              d_wy + (size_t)(b * Cc + by * 128) * Nn,
              2, blockIdx.x * 128, sm);
}

// ---------------- k_alpha: alpha = theta_w^T w_t ; bias_t = w_t . theta_b ----
__global__ void k_alpha(const float* __restrict__ theta_w,
                        const float* __restrict__ theta_b,
                        const float* __restrict__ cp_w) {
    int c = threadIdx.x;
    float a = 0.f;
    for (int ic = 0; ic < ICc; ic++) a += cp_w[ic] * theta_w[ic * Cc + c];
    d_alpha[c] = a;
    __shared__ float red[256];
    red[c] = (c < ICc) ? cp_w[c] * theta_b[c] : 0.f;
    __syncthreads();
    for (int s = 128; s > 0; s >>= 1) {
        if (c < s) red[c] += red[c + s];
        __syncthreads();
    }
    if (c == 0) d_bias_t[0] = red[0];
}

// ---------------- k_st (bandwidth version): s_t = alpha·x[:,n] + bias_t ------
// grid (Nn/32, Bn), block 256 = 8 channel-groups x 32 lanes.
__global__ __launch_bounds__(256) void k_st(const float* __restrict__ x) {
    __shared__ float part[8][33];
    int lane = threadIdx.x & 31, grp = threadIdx.x >> 5;
    int b = blockIdx.y, n = blockIdx.x * 32 + lane;
    const float* xb = x + (size_t)b * Cc * Nn + n;
    float s = 0.f;
#pragma unroll
    for (int j = 0; j < 32; j++) {
        int c = grp * 32 + j;
        s = fmaf(d_alpha[c], xb[(size_t)c * Nn], s);
    }
    part[grp][lane] = s;
    __syncthreads();
    if (grp == 0) {
        float acc = d_bias_t[0];
#pragma unroll
        for (int g = 0; g < 8; g++) acc += part[g][lane];
        d_st[b * Nn + n] = acc;
    }
}

// ---------------- pooling + transpose (g and phi) ----------------------------
__global__ void k_pool() {
    __shared__ float tile[32][33];
    int b = blockIdx.z;
    int ic0 = blockIdx.y * 32, m0 = blockIdx.x * 32;
    int tx = threadIdx.x, ty = threadIdx.y;
    int m = m0 + tx;
    int ph = m >> 5, pw = m & 31;
    size_t nb = (size_t)ph * 128 + pw * 2;

    {
        const float* base = d_gp + ((size_t)b * 2 * ICc + (ic0 + ty)) * Nn + nb;
        float v = fmaxf(fmaxf(base[0], base[1]), fmaxf(base[64], base[65]));
        tile[ty][tx] = v;
        __syncthreads();
        d_gT[((size_t)b * Mm + (m0 + ty)) * ICc + ic0 + tx] = tile[tx][ty];
        __syncthreads();
    }
    {
        const float* base = d_gp + ((size_t)b * 2 * ICc + ICc + (ic0 + ty)) * Nn + nb;
        float v = fmaxf(fmaxf(base[0], base[1]), fmaxf(base[64], base[65]));
        tile[ty][tx] = v;
        __syncthreads();
        d_phiT[((size_t)b * Mm + (m0 + ty)) * ICc + ic0 + tx] = tile[tx][ty];
    }
}

// ---------------- s_p[b][m] = w_p . phi_pool[b,:,m] --------------------------
__global__ void k_sp(const float* __restrict__ cp_w) {
    int gw = blockIdx.x * 8 + (threadIdx.x >> 5);
    int lane = threadIdx.x & 31;
    int b = gw >> 10, m = gw & 1023;
    const float* p = d_phiT + ((size_t)b * Mm + m) * ICc;
    const float* wp = cp_w + ICc;
    float s = p[lane] * wp[lane] + p[lane + 32] * wp[lane + 32] +
              p[lane + 64] * wp[lane + 64] + p[lane + 96] * wp[lane + 96];
#pragma unroll
    for (int off = 16; off > 0; off >>= 1) s += __shfl_xor_sync(0xffffffffu, s, off);
    if (lane == 0) d_sp[b * Mm + m] = s;
}

// ---------------- bitonic sort of s_p per batch, descending ------------------
__global__ void k_sort() {
    __shared__ float key[1024];
    __shared__ int   idx[1024];
    int tid = threadIdx.x, b = blockIdx.x;
    key[tid] = d_sp[b * Mm + tid];
    idx[tid] = tid;
    __syncthreads();
    for (int k = 2; k <= 1024; k <<= 1) {
        for (int j = k >> 1; j > 0; j >>= 1) {
            int ixj = tid ^ j;
            if (ixj > tid) {
                bool up = ((tid & k) == 0);
                float a = key[tid], c = key[ixj];
                bool sw = up ? (a < c) : (a > c);
                if (sw) {
                    key[tid] = c; key[ixj] = a;
                    int t = idx[tid]; idx[tid] = idx[ixj]; idx[ixj] = t;
                }
            }
            __syncthreads();
        }
    }
    d_ss[b * Mm + tid] = key[tid];
    d_perm[b * Mm + tid] = idx[tid];
}

// ---------------- prefix tables over sorted order ----------------------------
__global__ void k_p1() {
    __shared__ int   sperm[128];
    __shared__ float sval[128];
    int b = blockIdx.y, ch = blockIdx.x, ic = threadIdx.x;
    sperm[ic] = d_perm[b * Mm + ch * 128 + ic];
    sval[ic]  = d_ss[b * Mm + ch * 128 + ic];
    __syncthreads();
    float s1 = 0.f, s2 = 0.f;
#pragma unroll 4
    for (int j = 0; j < 128; j++) {
        float g = d_gT[((size_t)b * Mm + sperm[j]) * ICc + ic];
        s1 += g;
        s2 = fmaf(sval[j], g, s2);
    }
    d_cs1[((size_t)b * 8 + ch) * ICc + ic] = s1;
    d_cs2[((size_t)b * 8 + ch) * ICc + ic] = s2;
}

__global__ void k_p2() {
    __shared__ int   sperm[128];
    __shared__ float sval[128];
    int b = blockIdx.y, ch = blockIdx.x, ic = threadIdx.x;
    sperm[ic] = d_perm[b * Mm + ch * 128 + ic];
    sval[ic]  = d_ss[b * Mm + ch * 128 + ic];
    __syncthreads();
    float r1 = 0.f, r2 = 0.f;
    for (int cc = 0; cc < ch; cc++) {
        r1 += d_cs1[((size_t)b * 8 + cc) * ICc + ic];
        r2 += d_cs2[((size_t)b * 8 + cc) * ICc + ic];
    }
#pragma unroll 4
    for (int j = 0; j < 128; j++) {
        int kg = ch * 128 + j;
        d_G1[((size_t)b * 1025 + kg) * ICc + ic] = r1;
        d_G2[((size_t)b * 1025 + kg) * ICc + ic] = r2;
        float g = d_gT[((size_t)b * Mm + sperm[j]) * ICc + ic];
        r1 += g;
        r2 = fmaf(sval[j], g, r2);
    }
    if (ch == 7) {
        d_G1[((size_t)b * 1025 + 1024) * ICc + ic] = r1;
        d_G2[((size_t)b * 1025 + 1024) * ICc + ic] = r2;
    }
}

// ---------------- y: yT[b][ic][n] = (s_t[n]*G1[k(n),ic] + G2[k(n),ic]) / M ---
__global__ __launch_bounds__(256) void k_y() {
    extern __shared__ float tile[];          // [128][129]
    __shared__ int   s_lo[128];
    __shared__ float s_st[128];
    int t = threadIdx.x;
    int b = blockIdx.y, n0 = blockIdx.x * 128;

    if (t < 128) {
        float st = d_st[b * Nn + n0 + t];
        float tgt = -st;
        const float* ss = d_ss + b * Mm;
        int lo = 0, hi = 1024;
        while (lo < hi) {
            int mid = (lo + hi) >> 1;
            if (ss[mid] > tgt) lo = mid + 1; else hi = mid;
        }
        s_lo[t] = lo;
        s_st[t] = st;
    }
    __syncthreads();

    int ic = t & 127, nh = t >> 7;
    for (int j = 0; j < 64; j++) {
        int nl = nh * 64 + j;
        int lo = s_lo[nl];
        float st = s_st[nl];
        size_t gidx = ((size_t)b * 1025 + lo) * ICc + ic;
        tile[nl * 129 + ic] = (st * d_G1[gidx] + d_G2[gidx]) * (1.0f / 1024.0f);
    }
    __syncthreads();

    int nl = t & 127, half = t >> 7;
    for (int j = 0; j < 64; j++) {
        int ico = half * 64 + j;
        d_yT[((size_t)b * ICc + ico) * Nn + n0 + nl] = tile[nl * 129 + ico];
    }
}

// ---------------- BN stats per channel --------------------------------------
__global__ void k_bn(const float* __restrict__ gamma, const float* __restrict__ beta) {
    int c = blockIdx.x, tid = threadIdx.x;
    float s = 0.f, s2 = 0.f;
    for (int b = 0; b < Bn; b++) {
        const float* p = d_wy + ((size_t)b * Cc + c) * Nn;
        for (int n = tid; n < Nn; n += 256) {
            float v = p[n];
            s += v;
            s2 = fmaf(v, v, s2);
        }
    }
    __shared__ float r1[256], r2[256];
    r1[tid] = s; r2[tid] = s2;
    __syncthreads();
    for (int st = 128; st > 0; st >>= 1) {
        if (tid < st) { r1[tid] += r1[tid + st]; r2[tid] += r2[tid + st]; }
        __syncthreads();
    }
    if (tid == 0) {
        const float inv_cnt = 1.0f / (Bn * Nn);
        float mean = r1[0] * inv_cnt;
        float var = r2[0] * inv_cnt - mean * mean;
        float scale = rsqrtf(var + BN_EPS) * gamma[c];
        d_scale[c] = scale;
        d_shift[c] = beta[c] - mean * scale;
    }
}

// ---------------- final: out = wy*scale + shift + x --------------------------
__global__ void k_final(const float* __restrict__ x, float* __restrict__ out) {
    size_t i = ((size_t)blockIdx.x * 256 + threadIdx.x) * 4;
    int c = (int)((i / Nn) % Cc);
    float4 wv = *reinterpret_cast<const float4*>(d_wy + i);
    float4 xv = *reinterpret_cast<const float4*>(x + i);
    float sc = d_scale[c], sh = d_shift[c];
    float4 o;
    o.x = fmaf(wv.x, sc, sh) + xv.x;
    o.y = fmaf(wv.y, sc, sh) + xv.y;
    o.z = fmaf(wv.z, sc, sh) + xv.z;
    o.w = fmaf(wv.w, sc, sh) + xv.w;
    *reinterpret_cast<float4*>(out + i) = o;
}

// ---------------- launch -----------------------------------------------------
extern "C" void kernel_launch(void* const* d_in, const int* in_sizes, int n_in,
                              void* d_out, int out_size) {
    const float* x       = (const float*)d_in[0];
    const float* g_w     = (const float*)d_in[1];
    const float* g_b     = (const float*)d_in[2];
    const float* theta_w = (const float*)d_in[3];
    const float* theta_b = (const float*)d_in[4];
    const float* phi_w   = (const float*)d_in[5];
    const float* phi_b   = (const float*)d_in[6];
    const float* cp_w    = (const float*)d_in[7];
    const float* W_w     = (const float*)d_in[8];
    const float* W_b     = (const float*)d_in[9];
    const float* bn_g    = (const float*)d_in[10];
    const float* bn_b    = (const float*)d_in[11];
    float* out = (float*)d_out;

    static bool attr_done = false;
    if (!attr_done) {
        cudaFuncSetAttribute(k_mma1, cudaFuncAttributeMaxDynamicSharedMemorySize, GEMM_SMEM);
        cudaFuncSetAttribute(k_mma2, cudaFuncAttributeMaxDynamicSharedMemorySize, GEMM_SMEM);
        cudaFuncSetAttribute(k_y, cudaFuncAttributeMaxDynamicSharedMemorySize, 128 * 129 * 4);
        attr_done = true;
    }

    k_alpha<<<1, 256>>>(theta_w, theta_b, cp_w);
    k_prep<<<128, 256>>>(g_w, phi_w, W_w);
    k_mma1<<<dim3(32, 2, Bn), 256, GEMM_SMEM>>>(x, g_b, phi_b);
    k_st<<<dim3(Nn / 32, Bn), 256>>>(x);
    k_pool<<<dim3(32, 4, Bn), dim3(32, 32)>>>();
    k_sp<<<(Bn * Mm) / 8, 256>>>(cp_w);
    k_sort<<<Bn, 1024>>>();
    k_p1<<<dim3(8, Bn), 128>>>();
    k_p2<<<dim3(8, Bn), 128>>>();
    k_y<<<dim3(32, Bn), 256, 128 * 129 * 4>>>();
    k_mma2<<<dim3(32, 2, Bn), 256, GEMM_SMEM>>>(W_b);
    k_bn<<<Cc, 256>>>(bn_g, bn_b);
    k_final<<<(Bn * Cc * Nn) / (256 * 4), 256>>>(x, out);
}

// round 8
// speedup vs baseline: 1.4550x; 1.0575x over previous
#include <cuda_runtime.h>
#include <cuda_bf16.h>
#include <stdint.h>

// Problem dims
#define Bn  8
#define Cc  256
#define ICc 128
#define Nn  4096   // 64*64
#define Mm  1024   // 32*32
#define BN_EPS 1e-5f

// ---------------- scratch (__device__ globals; no allocation) ----------------
__device__ float d_alpha[Cc];
__device__ float d_bias_t[1];
__device__ float d_gp[Bn * 2 * ICc * Nn];   // g (o<128) + phi (o>=128) conv outputs
__device__ float d_st[Bn * Nn];
__device__ float d_gT[Bn * Mm * ICc];       // pooled g, (b, m, ic)
__device__ float d_phiT[Bn * Mm * ICc];     // pooled phi, (b, m, ic)
__device__ float d_sp[Bn * Mm];
__device__ float d_ss[Bn * Mm];             // s_p sorted descending
__device__ int   d_perm[Bn * Mm];
__device__ float d_cs1[Bn * 8 * ICc];
__device__ float d_cs2[Bn * 8 * ICc];
__device__ float d_G1[Bn * 1025 * ICc];
__device__ float d_G2[Bn * 1025 * ICc];
__device__ float d_wy[Bn * Cc * Nn];
__device__ float d_scale[Cc];
__device__ float d_shift[Cc];

// pre-split bf16 operands (hi/lo)
__device__ __align__(16) __nv_bfloat16 d_wgh[ICc * Cc];
__device__ __align__(16) __nv_bfloat16 d_wgl[ICc * Cc];
__device__ __align__(16) __nv_bfloat16 d_wph[ICc * Cc];
__device__ __align__(16) __nv_bfloat16 d_wpl[ICc * Cc];
__device__ __align__(16) __nv_bfloat16 d_wWh[Cc * ICc];
__device__ __align__(16) __nv_bfloat16 d_wWl[Cc * ICc];
__device__ __align__(16) __nv_bfloat16 d_xh[Bn * Cc * Nn];
__device__ __align__(16) __nv_bfloat16 d_xl[Bn * Cc * Nn];
__device__ __align__(16) __nv_bfloat16 d_yh[Bn * ICc * Nn];
__device__ __align__(16) __nv_bfloat16 d_yl[Bn * ICc * Nn];

// ================= mma.sync / cp.async helpers (sm_80+ baseline) =============
__device__ __forceinline__ uint32_t smem_u32(const void* p) {
    uint32_t a;
    asm("{ .reg .u64 t; cvta.to.shared.u64 t, %1; cvt.u32.u64 %0, t; }" : "=r"(a) : "l"(p));
    return a;
}
__device__ __forceinline__ void cpa16(uint32_t smem, const void* g) {
    asm volatile("cp.async.cg.shared.global [%0], [%1], 16;" :: "r"(smem), "l"(g));
}
#define CPA_COMMIT() asm volatile("cp.async.commit_group;" ::: "memory")
#define CPA_WAIT0()  asm volatile("cp.async.wait_group 0;" ::: "memory")

__device__ __forceinline__ void ldsm4(uint32_t* r, uint32_t addr) {
    asm volatile("ldmatrix.sync.aligned.m8n8.x4.shared.b16 {%0,%1,%2,%3}, [%4];"
                 : "=r"(r[0]), "=r"(r[1]), "=r"(r[2]), "=r"(r[3]) : "r"(addr));
}
__device__ __forceinline__ void ldsm4t(uint32_t* r, uint32_t addr) {
    asm volatile("ldmatrix.sync.aligned.m8n8.x4.trans.shared.b16 {%0,%1,%2,%3}, [%4];"
                 : "=r"(r[0]), "=r"(r[1]), "=r"(r[2]), "=r"(r[3]) : "r"(addr));
}
__device__ __forceinline__ void mma16816(float* d, const uint32_t* a, const uint32_t* b) {
    asm volatile("mma.sync.aligned.m16n8k16.row.col.f32.bf16.bf16.f32 "
                 "{%0,%1,%2,%3},{%4,%5,%6,%7},{%8,%9},{%0,%1,%2,%3};"
                 : "+f"(d[0]), "+f"(d[1]), "+f"(d[2]), "+f"(d[3])
                 : "r"(a[0]), "r"(a[1]), "r"(a[2]), "r"(a[3]), "r"(b[0]), "r"(b[1]));
}

// split fp32 -> (hi,lo) bf16; pack two values into bf16x2 words
__device__ __forceinline__ void pack_split(float a, float b, uint32_t& hp, uint32_t& lp) {
    __nv_bfloat16 ha = __float2bfloat16(a), hb = __float2bfloat16(b);
    __nv_bfloat16 la = __float2bfloat16(a - __bfloat162float(ha));
    __nv_bfloat16 lb = __float2bfloat16(b - __bfloat162float(hb));
    __nv_bfloat162 h2(ha, hb), l2(la, lb);
    hp = *reinterpret_cast<uint32_t*>(&h2);
    lp = *reinterpret_cast<uint32_t*>(&l2);
}

// ---------------- pipelined warp-MMA GEMM core -------------------------------
// C[128, Nn-slice] = A[128, K] * B[K, Nn-slice] + bias; ALL operands pre-split
// bf16 hi/lo in gmem. 2-stage cp.async pipeline, stage = 64KB:
//   Ah @0 (128x64 bf16, 128B rows, swizzled), Al @16K, Bh @32K (64x128, 256B
//   rows, swizzled), Bl @48K.
// Block: 256 thr = 8 warps (2M x 4N), warp tile 64x32. K chunk = 64.
#define STAGE_BYTES 65536
#define GEMM_SMEM   (2 * STAGE_BYTES)

__device__ __forceinline__ void issue_chunk(const __nv_bfloat16* __restrict__ Ahsrc,
                                            const __nv_bfloat16* __restrict__ Alsrc,
                                            int lda,
                                            const __nv_bfloat16* __restrict__ Bhsrc,
                                            const __nv_bfloat16* __restrict__ Blsrc,
                                            int k0, int n0, uint32_t sb, int t) {
    {   // A: thread -> row r, half h (32 cols); 4 x 16B per buffer
        int r = t >> 1, h = t & 1;
        const __nv_bfloat16* gh = Ahsrc + (size_t)r * lda + k0 + h * 32;
        const __nv_bfloat16* gl = Alsrc + (size_t)r * lda + k0 + h * 32;
        uint32_t sw = (uint32_t)(r & 7) << 4;
        uint32_t base = (uint32_t)r * 128 + h * 64;
#pragma unroll
        for (int j = 0; j < 4; j++) {
            uint32_t off = (base + 16u * j) ^ sw;
            cpa16(sb + off, gh + j * 8);
            cpa16(sb + 16384 + off, gl + j * 8);
        }
    }
    {   // B: thread -> k row r, quarter q (32 cols); 4 x 16B per buffer
        int r = t >> 2, q = t & 3;
        const __nv_bfloat16* gh = Bhsrc + (size_t)(k0 + r) * Nn + n0 + q * 32;
        const __nv_bfloat16* gl = Blsrc + (size_t)(k0 + r) * Nn + n0 + q * 32;
        uint32_t sw = (uint32_t)(r & 7) << 4;
        uint32_t base = (uint32_t)r * 256 + q * 64;
#pragma unroll
        for (int j = 0; j < 4; j++) {
            uint32_t off = (base + 16u * j) ^ sw;
            cpa16(sb + 32768 + off, gh + j * 8);
            cpa16(sb + 49152 + off, gl + j * 8);
        }
    }
}

__device__ __forceinline__ void gemm_core(const __nv_bfloat16* __restrict__ Ahsrc,
                                          const __nv_bfloat16* __restrict__ Alsrc,
                                          int lda,
                                          const float* __restrict__ bias,
                                          const __nv_bfloat16* __restrict__ Bhsrc,
                                          const __nv_bfloat16* __restrict__ Blsrc,
                                          float* __restrict__ C,
                                          int nchunks, int n0, char* sm) {
    const uint32_t smB = smem_u32(sm);
    const int t = threadIdx.x;
    const int warp = t >> 5, lane = t & 31;
    const int wm = (warp >> 2) * 64;   // warp M offset
    const int wn = (warp & 3) * 32;    // warp N offset

    float acc[16][4];
#pragma unroll
    for (int i = 0; i < 16; i++)
#pragma unroll
        for (int j = 0; j < 4; j++) acc[i][j] = 0.f;

    issue_chunk(Ahsrc, Alsrc, lda, Bhsrc, Blsrc, 0, n0, smB, t);
    CPA_COMMIT();

    for (int ch = 0; ch < nchunks; ch++) {
        CPA_WAIT0();
        __syncthreads();
        if (ch + 1 < nchunks) {
            issue_chunk(Ahsrc, Alsrc, lda, Bhsrc, Blsrc, (ch + 1) * 64, n0,
                        smB + (uint32_t)((ch + 1) & 1) * STAGE_BYTES, t);
            CPA_COMMIT();
        }
        const uint32_t sb = smB + (uint32_t)(ch & 1) * STAGE_BYTES;

#pragma unroll
        for (int ks = 0; ks < 4; ks++) {
            uint32_t bh[8], bl[8];
#pragma unroll
            for (int p = 0; p < 2; p++) {
                uint32_t krow = (uint32_t)(ks * 16 + (lane & 15));
                uint32_t off = krow * 256 + (uint32_t)(wn + p * 16) * 2 + ((lane >> 4) << 4);
                off ^= (krow & 7) << 4;
                ldsm4t(bh + p * 4, sb + 32768 + off);
                ldsm4t(bl + p * 4, sb + 49152 + off);
            }
#pragma unroll
            for (int mi = 0; mi < 4; mi++) {
                uint32_t ah[4], al[4];
                uint32_t row = (uint32_t)(wm + mi * 16 + (lane & 15));
                uint32_t off = row * 128 + (uint32_t)(ks * 32) + ((lane >> 4) << 4);
                off ^= (row & 7) << 4;
                ldsm4(ah, sb + off);
                ldsm4(al, sb + 16384 + off);
#pragma unroll
                for (int ni = 0; ni < 4; ni++) {
                    const uint32_t* fh = &bh[(ni >> 1) * 4 + (ni & 1) * 2];
                    const uint32_t* fl = &bl[(ni >> 1) * 4 + (ni & 1) * 2];
                    float* d = acc[mi * 4 + ni];
                    mma16816(d, ah, fh);
                    mma16816(d, ah, fl);
                    mma16816(d, al, fh);
                }
            }
        }
    }

    // ---- epilogue: bias + store fp32
#pragma unroll
    for (int mi = 0; mi < 4; mi++) {
        int o0 = wm + mi * 16 + (lane >> 2);
        float bv0 = bias[o0], bv1 = bias[o0 + 8];
#pragma unroll
        for (int ni = 0; ni < 4; ni++) {
            int col = n0 + wn + ni * 8 + (lane & 3) * 2;
            const float* d = acc[mi * 4 + ni];
            float2 v0 = make_float2(d[0] + bv0, d[1] + bv0);
            float2 v1 = make_float2(d[2] + bv1, d[3] + bv1);
            *reinterpret_cast<float2*>(C + (size_t)o0 * Nn + col) = v0;
            *reinterpret_cast<float2*>(C + (size_t)(o0 + 8) * Nn + col) = v1;
        }
    }
}

// ---------------- weight pre-split -------------------------------------------
__global__ void k_prep(const float* __restrict__ g_w, const float* __restrict__ phi_w,
                       const float* __restrict__ W_w) {
    int i = blockIdx.x * 256 + threadIdx.x;   // < 32768
    float v = g_w[i];
    __nv_bfloat16 h = __float2bfloat16(v);
    d_wgh[i] = h; d_wgl[i] = __float2bfloat16(v - __bfloat162float(h));
    v = phi_w[i]; h = __float2bfloat16(v);
    d_wph[i] = h; d_wpl[i] = __float2bfloat16(v - __bfloat162float(h));
    v = W_w[i]; h = __float2bfloat16(v);
    d_wWh[i] = h; d_wWl[i] = __float2bfloat16(v - __bfloat162float(h));
}

// ---------------- x pre-split: fp32 (b,c,n) -> bf16 hi/lo --------------------
__global__ void k_xsplit(const float* __restrict__ x) {
    size_t i = ((size_t)blockIdx.x * 256 + threadIdx.x) * 4;
    float4 v = *reinterpret_cast<const float4*>(x + i);
    uint32_t h0, l0, h1, l1;
    pack_split(v.x, v.y, h0, l0);
    pack_split(v.z, v.w, h1, l1);
    *reinterpret_cast<uint2*>(d_xh + i) = make_uint2(h0, h1);
    *reinterpret_cast<uint2*>(d_xl + i) = make_uint2(l0, l1);
}

// GEMM1: d_gp[b][which*128+o][n] = (g_w|phi_w)[o,:]·x[b,:,n] + bias[o]; K=256
__global__ __launch_bounds__(256) void k_mma1(const float* __restrict__ g_b,
                                              const float* __restrict__ phi_b) {
    extern __shared__ char sm[];
    int which = blockIdx.y, b = blockIdx.z;
    gemm_core(which ? d_wph : d_wgh, which ? d_wpl : d_wgl, Cc,
              which ? phi_b : g_b,
              d_xh + (size_t)b * Cc * Nn, d_xl + (size_t)b * Cc * Nn,
              d_gp + (size_t)(b * 2 + which) * ICc * Nn,
              4, blockIdx.x * 128, sm);
}

// GEMM2: d_wy[b][by*128+c][n] = W_w[by*128+c,:]·yT[b,:,n] + W_b; K=128
__global__ __launch_bounds__(256) void k_mma2(const float* __restrict__ W_b) {
    extern __shared__ char sm[];
    int by = blockIdx.y, b = blockIdx.z;
    gemm_core(d_wWh + (size_t)by * 128 * ICc, d_wWl + (size_t)by * 128 * ICc, ICc,
              W_b + by * 128,
              d_yh + (size_t)b * ICc * Nn, d_yl + (size_t)b * ICc * Nn,
              d_wy + (size_t)(b * Cc + by * 128) * Nn,
              2, blockIdx.x * 128, sm);
}

// ---------------- k_alpha: alpha = theta_w^T w_t ; bias_t = w_t . theta_b ----
__global__ void k_alpha(const float* __restrict__ theta_w,
                        const float* __restrict__ theta_b,
                        const float* __restrict__ cp_w) {
    int c = threadIdx.x;
    float a = 0.f;
    for (int ic = 0; ic < ICc; ic++) a += cp_w[ic] * theta_w[ic * Cc + c];
    d_alpha[c] = a;
    __shared__ float red[256];
    red[c] = (c < ICc) ? cp_w[c] * theta_b[c] : 0.f;
    __syncthreads();
    for (int s = 128; s > 0; s >>= 1) {
        if (c < s) red[c] += red[c + s];
        __syncthreads();
    }
    if (c == 0) d_bias_t[0] = red[0];
}

// ---------------- k_st (bandwidth version): s_t = alpha·x[:,n] + bias_t ------
__global__ __launch_bounds__(256) void k_st(const float* __restrict__ x) {
    __shared__ float part[8][33];
    int lane = threadIdx.x & 31, grp = threadIdx.x >> 5;
    int b = blockIdx.y, n = blockIdx.x * 32 + lane;
    const float* xb = x + (size_t)b * Cc * Nn + n;
    float s = 0.f;
#pragma unroll
    for (int j = 0; j < 32; j++) {
        int c = grp * 32 + j;
        s = fmaf(d_alpha[c], xb[(size_t)c * Nn], s);
    }
    part[grp][lane] = s;
    __syncthreads();
    if (grp == 0) {
        float acc = d_bias_t[0];
#pragma unroll
        for (int g = 0; g < 8; g++) acc += part[g][lane];
        d_st[b * Nn + n] = acc;
    }
}

// ---------------- pooling + transpose (g and phi) ----------------------------
__global__ void k_pool() {
    __shared__ float tile[32][33];
    int b = blockIdx.z;
    int ic0 = blockIdx.y * 32, m0 = blockIdx.x * 32;
    int tx = threadIdx.x, ty = threadIdx.y;
    int m = m0 + tx;
    int ph = m >> 5, pw = m & 31;
    size_t nb = (size_t)ph * 128 + pw * 2;

    {
        const float* base = d_gp + ((size_t)b * 2 * ICc + (ic0 + ty)) * Nn + nb;
        float v = fmaxf(fmaxf(base[0], base[1]), fmaxf(base[64], base[65]));
        tile[ty][tx] = v;
        __syncthreads();
        d_gT[((size_t)b * Mm + (m0 + ty)) * ICc + ic0 + tx] = tile[tx][ty];
        __syncthreads();
    }
    {
        const float* base = d_gp + ((size_t)b * 2 * ICc + ICc + (ic0 + ty)) * Nn + nb;
        float v = fmaxf(fmaxf(base[0], base[1]), fmaxf(base[64], base[65]));
        tile[ty][tx] = v;
        __syncthreads();
        d_phiT[((size_t)b * Mm + (m0 + ty)) * ICc + ic0 + tx] = tile[tx][ty];
    }
}

// ---------------- s_p[b][m] = w_p . phi_pool[b,:,m] --------------------------
__global__ void k_sp(const float* __restrict__ cp_w) {
    int gw = blockIdx.x * 8 + (threadIdx.x >> 5);
    int lane = threadIdx.x & 31;
    int b = gw >> 10, m = gw & 1023;
    const float* p = d_phiT + ((size_t)b * Mm + m) * ICc;
    const float* wp = cp_w + ICc;
    float s = p[lane] * wp[lane] + p[lane + 32] * wp[lane + 32] +
              p[lane + 64] * wp[lane + 64] + p[lane + 96] * wp[lane + 96];
#pragma unroll
    for (int off = 16; off > 0; off >>= 1) s += __shfl_xor_sync(0xffffffffu, s, off);
    if (lane == 0) d_sp[b * Mm + m] = s;
}

// ---------------- bitonic sort of s_p per batch, descending ------------------
__global__ void k_sort() {
    __shared__ float key[1024];
    __shared__ int   idx[1024];
    int tid = threadIdx.x, b = blockIdx.x;
    key[tid] = d_sp[b * Mm + tid];
    idx[tid] = tid;
    __syncthreads();
    for (int k = 2; k <= 1024; k <<= 1) {
        for (int j = k >> 1; j > 0; j >>= 1) {
            int ixj = tid ^ j;
            if (ixj > tid) {
                bool up = ((tid & k) == 0);
                float a = key[tid], c = key[ixj];
                bool sw = up ? (a < c) : (a > c);
                if (sw) {
                    key[tid] = c; key[ixj] = a;
                    int t = idx[tid]; idx[tid] = idx[ixj]; idx[ixj] = t;
                }
            }
            __syncthreads();
        }
    }
    d_ss[b * Mm + tid] = key[tid];
    d_perm[b * Mm + tid] = idx[tid];
}

// ---------------- prefix tables over sorted order ----------------------------
__global__ void k_p1() {
    __shared__ int   sperm[128];
    __shared__ float sval[128];
    int b = blockIdx.y, ch = blockIdx.x, ic = threadIdx.x;
    sperm[ic] = d_perm[b * Mm + ch * 128 + ic];
    sval[ic]  = d_ss[b * Mm + ch * 128 + ic];
    __syncthreads();
    float s1 = 0.f, s2 = 0.f;
#pragma unroll 4
    for (int j = 0; j < 128; j++) {
        float g = d_gT[((size_t)b * Mm + sperm[j]) * ICc + ic];
        s1 += g;
        s2 = fmaf(sval[j], g, s2);
    }
    d_cs1[((size_t)b * 8 + ch) * ICc + ic] = s1;
    d_cs2[((size_t)b * 8 + ch) * ICc + ic] = s2;
}

__global__ void k_p2() {
    __shared__ int   sperm[128];
    __shared__ float sval[128];
    int b = blockIdx.y, ch = blockIdx.x, ic = threadIdx.x;
    sperm[ic] = d_perm[b * Mm + ch * 128 + ic];
    sval[ic]  = d_ss[b * Mm + ch * 128 + ic];
    __syncthreads();
    float r1 = 0.f, r2 = 0.f;
    for (int cc = 0; cc < ch; cc++) {
        r1 += d_cs1[((size_t)b * 8 + cc) * ICc + ic];
        r2 += d_cs2[((size_t)b * 8 + cc) * ICc + ic];
    }
#pragma unroll 4
    for (int j = 0; j < 128; j++) {
        int kg = ch * 128 + j;
        d_G1[((size_t)b * 1025 + kg) * ICc + ic] = r1;
        d_G2[((size_t)b * 1025 + kg) * ICc + ic] = r2;
        float g = d_gT[((size_t)b * Mm + sperm[j]) * ICc + ic];
        r1 += g;
        r2 = fmaf(sval[j], g, r2);
    }
    if (ch == 7) {
        d_G1[((size_t)b * 1025 + 1024) * ICc + ic] = r1;
        d_G2[((size_t)b * 1025 + 1024) * ICc + ic] = r2;
    }
}

// ---------------- y: yT[b][ic][n] (split bf16) -------------------------------
__global__ __launch_bounds__(256) void k_y() {
    extern __shared__ float tile[];          // [128][129]
    __shared__ int   s_lo[128];
    __shared__ float s_st[128];
    int t = threadIdx.x;
    int b = blockIdx.y, n0 = blockIdx.x * 128;

    if (t < 128) {
        float st = d_st[b * Nn + n0 + t];
        float tgt = -st;
        const float* ss = d_ss + b * Mm;
        int lo = 0, hi = 1024;
        while (lo < hi) {
            int mid = (lo + hi) >> 1;
            if (ss[mid] > tgt) lo = mid + 1; else hi = mid;
        }
        s_lo[t] = lo;
        s_st[t] = st;
    }
    __syncthreads();

    int ic = t & 127, nh = t >> 7;
    for (int j = 0; j < 64; j++) {
        int nl = nh * 64 + j;
        int lo = s_lo[nl];
        float st = s_st[nl];
        size_t gidx = ((size_t)b * 1025 + lo) * ICc + ic;
        tile[nl * 129 + ic] = (st * d_G1[gidx] + d_G2[gidx]) * (1.0f / 1024.0f);
    }
    __syncthreads();

    int nl = t & 127, half = t >> 7;
    for (int j = 0; j < 64; j++) {
        int ico = half * 64 + j;
        float v = tile[nl * 129 + ico];
        __nv_bfloat16 h = __float2bfloat16(v);
        size_t idx = ((size_t)b * ICc + ico) * Nn + n0 + nl;
        d_yh[idx] = h;
        d_yl[idx] = __float2bfloat16(v - __bfloat162float(h));
    }
}

// ---------------- BN stats per channel --------------------------------------
__global__ void k_bn(const float* __restrict__ gamma, const float* __restrict__ beta) {
    int c = blockIdx.x, tid = threadIdx.x;
    float s = 0.f, s2 = 0.f;
    for (int b = 0; b < Bn; b++) {
        const float* p = d_wy + ((size_t)b * Cc + c) * Nn;
        for (int n = tid; n < Nn; n += 256) {
            float v = p[n];
            s += v;
            s2 = fmaf(v, v, s2);
        }
    }
    __shared__ float r1[256], r2[256];
    r1[tid] = s; r2[tid] = s2;
    __syncthreads();
    for (int st = 128; st > 0; st >>= 1) {
        if (tid < st) { r1[tid] += r1[tid + st]; r2[tid] += r2[tid + st]; }
        __syncthreads();
    }
    if (tid == 0) {
        const float inv_cnt = 1.0f / (Bn * Nn);
        float mean = r1[0] * inv_cnt;
        float var = r2[0] * inv_cnt - mean * mean;
        float scale = rsqrtf(var + BN_EPS) * gamma[c];
        d_scale[c] = scale;
        d_shift[c] = beta[c] - mean * scale;
    }
}

// ---------------- final: out = wy*scale + shift + x --------------------------
__global__ void k_final(const float* __restrict__ x, float* __restrict__ out) {
    size_t i = ((size_t)blockIdx.x * 256 + threadIdx.x) * 4;
    int c = (int)((i / Nn) % Cc);
    float4 wv = *reinterpret_cast<const float4*>(d_wy + i);
    float4 xv = *reinterpret_cast<const float4*>(x + i);
    float sc = d_scale[c], sh = d_shift[c];
    float4 o;
    o.x = fmaf(wv.x, sc, sh) + xv.x;
    o.y = fmaf(wv.y, sc, sh) + xv.y;
    o.z = fmaf(wv.z, sc, sh) + xv.z;
    o.w = fmaf(wv.w, sc, sh) + xv.w;
    *reinterpret_cast<float4*>(out + i) = o;
}

// ---------------- launch -----------------------------------------------------
extern "C" void kernel_launch(void* const* d_in, const int* in_sizes, int n_in,
                              void* d_out, int out_size) {
    const float* x       = (const float*)d_in[0];
    const float* g_w     = (const float*)d_in[1];
    const float* g_b     = (const float*)d_in[2];
    const float* theta_w = (const float*)d_in[3];
    const float* theta_b = (const float*)d_in[4];
    const float* phi_w   = (const float*)d_in[5];
    const float* phi_b   = (const float*)d_in[6];
    const float* cp_w    = (const float*)d_in[7];
    const float* W_w     = (const float*)d_in[8];
    const float* W_b     = (const float*)d_in[9];
    const float* bn_g    = (const float*)d_in[10];
    const float* bn_b    = (const float*)d_in[11];
    float* out = (float*)d_out;

    static bool attr_done = false;
    if (!attr_done) {
        cudaFuncSetAttribute(k_mma1, cudaFuncAttributeMaxDynamicSharedMemorySize, GEMM_SMEM);
        cudaFuncSetAttribute(k_mma2, cudaFuncAttributeMaxDynamicSharedMemorySize, GEMM_SMEM);
        cudaFuncSetAttribute(k_y, cudaFuncAttributeMaxDynamicSharedMemorySize, 128 * 129 * 4);
        attr_done = true;
    }

    k_alpha<<<1, 256>>>(theta_w, theta_b, cp_w);
    k_prep<<<128, 256>>>(g_w, phi_w, W_w);
    k_xsplit<<<8192, 256>>>(x);
    k_mma1<<<dim3(32, 2, Bn), 256, GEMM_SMEM>>>(g_b, phi_b);
    k_st<<<dim3(Nn / 32, Bn), 256>>>(x);
    k_pool<<<dim3(32, 4, Bn), dim3(32, 32)>>>();
    k_sp<<<(Bn * Mm) / 8, 256>>>(cp_w);
    k_sort<<<Bn, 1024>>>();
    k_p1<<<dim3(8, Bn), 128>>>();
    k_p2<<<dim3(8, Bn), 128>>>();
    k_y<<<dim3(32, Bn), 256, 128 * 129 * 4>>>();
    k_mma2<<<dim3(32, 2, Bn), 256, GEMM_SMEM>>>(W_b);
    k_bn<<<Cc, 256>>>(bn_g, bn_b);
    k_final<<<(Bn * Cc * Nn) / (256 * 4), 256>>>(x, out);
}

// round 9
// speedup vs baseline: 1.6569x; 1.1388x over previous
#include <cuda_runtime.h>
#include <cuda_bf16.h>
#include <stdint.h>

// Problem dims
#define Bn  8
#define Cc  256
#define ICc 128
#define Nn  4096   // 64*64
#define Mm  1024   // 32*32
#define BN_EPS 1e-5f

// ---------------- scratch (__device__ globals; no allocation) ----------------
__device__ float d_alpha[Cc];
__device__ float d_bias_t[1];
__device__ float d_gp[Bn * 2 * ICc * Nn];   // g (o<128) + phi (o>=128) conv outputs
__device__ float d_st[Bn * Nn];
__device__ float d_gT[Bn * Mm * ICc];       // pooled g, (b, m, ic)
__device__ float d_phiT[Bn * Mm * ICc];     // pooled phi, (b, m, ic)
__device__ float d_sp[Bn * Mm];
__device__ float d_ss[Bn * Mm];             // s_p sorted descending
__device__ int   d_perm[Bn * Mm];
__device__ float d_cs1[Bn * 8 * ICc];
__device__ float d_cs2[Bn * 8 * ICc];
__device__ float d_G1[Bn * 1025 * ICc];
__device__ float d_G2[Bn * 1025 * ICc];
__device__ float d_wy[Bn * Cc * Nn];
__device__ float d_scale[Cc];
__device__ float d_shift[Cc];

// pre-split bf16 operands (hi/lo)
__device__ __align__(16) __nv_bfloat16 d_wgh[ICc * Cc];
__device__ __align__(16) __nv_bfloat16 d_wgl[ICc * Cc];
__device__ __align__(16) __nv_bfloat16 d_wph[ICc * Cc];
__device__ __align__(16) __nv_bfloat16 d_wpl[ICc * Cc];
__device__ __align__(16) __nv_bfloat16 d_wWh[Cc * ICc];
__device__ __align__(16) __nv_bfloat16 d_wWl[Cc * ICc];
__device__ __align__(16) __nv_bfloat16 d_xh[Bn * Cc * Nn];
__device__ __align__(16) __nv_bfloat16 d_xl[Bn * Cc * Nn];
__device__ __align__(16) __nv_bfloat16 d_yh[Bn * ICc * Nn];
__device__ __align__(16) __nv_bfloat16 d_yl[Bn * ICc * Nn];

// ================= mma.sync / cp.async helpers (sm_80+ baseline) =============
__device__ __forceinline__ uint32_t smem_u32(const void* p) {
    uint32_t a;
    asm("{ .reg .u64 t; cvta.to.shared.u64 t, %1; cvt.u32.u64 %0, t; }" : "=r"(a) : "l"(p));
    return a;
}
__device__ __forceinline__ void cpa16(uint32_t smem, const void* g) {
    asm volatile("cp.async.cg.shared.global [%0], [%1], 16;" :: "r"(smem), "l"(g));
}
#define CPA_COMMIT() asm volatile("cp.async.commit_group;" ::: "memory")
__device__ __forceinline__ void cpa_wait(int n) {
    if (n <= 0)      asm volatile("cp.async.wait_group 0;" ::: "memory");
    else if (n == 1) asm volatile("cp.async.wait_group 1;" ::: "memory");
    else             asm volatile("cp.async.wait_group 2;" ::: "memory");
}

__device__ __forceinline__ void ldsm4(uint32_t* r, uint32_t addr) {
    asm volatile("ldmatrix.sync.aligned.m8n8.x4.shared.b16 {%0,%1,%2,%3}, [%4];"
                 : "=r"(r[0]), "=r"(r[1]), "=r"(r[2]), "=r"(r[3]) : "r"(addr));
}
__device__ __forceinline__ void ldsm4t(uint32_t* r, uint32_t addr) {
    asm volatile("ldmatrix.sync.aligned.m8n8.x4.trans.shared.b16 {%0,%1,%2,%3}, [%4];"
                 : "=r"(r[0]), "=r"(r[1]), "=r"(r[2]), "=r"(r[3]) : "r"(addr));
}
__device__ __forceinline__ void mma16816(float* d, const uint32_t* a, const uint32_t* b) {
    asm volatile("mma.sync.aligned.m16n8k16.row.col.f32.bf16.bf16.f32 "
                 "{%0,%1,%2,%3},{%4,%5,%6,%7},{%8,%9},{%0,%1,%2,%3};"
                 : "+f"(d[0]), "+f"(d[1]), "+f"(d[2]), "+f"(d[3])
                 : "r"(a[0]), "r"(a[1]), "r"(a[2]), "r"(a[3]), "r"(b[0]), "r"(b[1]));
}

// split fp32 -> (hi,lo) bf16; pack two values into bf16x2 words
__device__ __forceinline__ void pack_split(float a, float b, uint32_t& hp, uint32_t& lp) {
    __nv_bfloat16 ha = __float2bfloat16(a), hb = __float2bfloat16(b);
    __nv_bfloat16 la = __float2bfloat16(a - __bfloat162float(ha));
    __nv_bfloat16 lb = __float2bfloat16(b - __bfloat162float(hb));
    __nv_bfloat162 h2(ha, hb), l2(la, lb);
    hp = *reinterpret_cast<uint32_t*>(&h2);
    lp = *reinterpret_cast<uint32_t*>(&l2);
}

// ---------------- deep-pipelined warp-MMA GEMM core --------------------------
// C[128, Nn-slice] = A[128, K] * B[K, Nn-slice] + bias; all operands pre-split
// bf16 hi/lo in gmem. 4-stage cp.async ring, K chunk = 32, stage = 32KB:
//   Ah @0 (128x32 bf16, 64B rows), Al @8K, Bh @16K (32x128, 256B rows), Bl @24K.
// Block: 512 thr = 16 warps (4M x 4N), warp tile 32x32.
#define STAGE_BYTES 32768
#define NSTAGES 4
#define GEMM_SMEM (NSTAGES * STAGE_BYTES)

__device__ __forceinline__ void issue_chunk(const __nv_bfloat16* __restrict__ Ahsrc,
                                            const __nv_bfloat16* __restrict__ Alsrc,
                                            int lda,
                                            const __nv_bfloat16* __restrict__ Bhsrc,
                                            const __nv_bfloat16* __restrict__ Blsrc,
                                            int k0, int n0, uint32_t sb, int t) {
    {   // A: 128 rows x 32 cols, 64B rows; thread -> row r = t>>2, seg s = t&3
        int r = t >> 2, s = t & 3;
        uint32_t off = ((uint32_t)r * 64 + (uint32_t)s * 16) ^ (((uint32_t)(r >> 1) & 3) << 4);
        const __nv_bfloat16* gh = Ahsrc + (size_t)r * lda + k0 + s * 8;
        const __nv_bfloat16* gl = Alsrc + (size_t)r * lda + k0 + s * 8;
        cpa16(sb + off, gh);
        cpa16(sb + 8192 + off, gl);
    }
    {   // B: 32 rows x 128 cols, 256B rows; thread -> row r = t>>4, seg q = t&15
        int r = t >> 4, q = t & 15;
        uint32_t off = ((uint32_t)r * 256 + (uint32_t)q * 16) ^ (((uint32_t)r & 7) << 4);
        const __nv_bfloat16* gh = Bhsrc + (size_t)(k0 + r) * Nn + n0 + q * 8;
        const __nv_bfloat16* gl = Blsrc + (size_t)(k0 + r) * Nn + n0 + q * 8;
        cpa16(sb + 16384 + off, gh);
        cpa16(sb + 24576 + off, gl);
    }
}

template <int NCH>
__device__ __forceinline__ void gemm_core(const __nv_bfloat16* __restrict__ Ahsrc,
                                          const __nv_bfloat16* __restrict__ Alsrc,
                                          int lda,
                                          const float* __restrict__ bias,
                                          const __nv_bfloat16* __restrict__ Bhsrc,
                                          const __nv_bfloat16* __restrict__ Blsrc,
                                          float* __restrict__ C,
                                          int n0, char* sm) {
    const uint32_t smB = smem_u32(sm);
    const int t = threadIdx.x;
    const int warp = t >> 5, lane = t & 31;
    const int wm = (warp >> 2) * 32;   // warp M offset
    const int wn = (warp & 3) * 32;    // warp N offset

    float acc[8][4];
#pragma unroll
    for (int i = 0; i < 8; i++)
#pragma unroll
        for (int j = 0; j < 4; j++) acc[i][j] = 0.f;

#pragma unroll
    for (int p = 0; p < 3 && p < NCH; p++) {
        issue_chunk(Ahsrc, Alsrc, lda, Bhsrc, Blsrc, p * 32, n0,
                    smB + (uint32_t)p * STAGE_BYTES, t);
        CPA_COMMIT();
    }

#pragma unroll
    for (int ch = 0; ch < NCH; ch++) {
        cpa_wait(NCH - ch - 1 < 2 ? NCH - ch - 1 : 2);
        __syncthreads();
        if (ch + 3 < NCH) {
            issue_chunk(Ahsrc, Alsrc, lda, Bhsrc, Blsrc, (ch + 3) * 32, n0,
                        smB + (uint32_t)((ch + 3) & (NSTAGES - 1)) * STAGE_BYTES, t);
            CPA_COMMIT();
        }
        const uint32_t sb = smB + (uint32_t)(ch & (NSTAGES - 1)) * STAGE_BYTES;

#pragma unroll
        for (int ks = 0; ks < 2; ks++) {
            uint32_t bh[8], bl[8];
#pragma unroll
            for (int p = 0; p < 2; p++) {
                uint32_t krow = (uint32_t)(ks * 16 + (lane & 15));
                uint32_t off = krow * 256 + (uint32_t)(wn + p * 16) * 2 + ((lane >> 4) << 4);
                off ^= (krow & 7) << 4;
                ldsm4t(bh + p * 4, sb + 16384 + off);
                ldsm4t(bl + p * 4, sb + 24576 + off);
            }
#pragma unroll
            for (int mi = 0; mi < 2; mi++) {
                uint32_t ah[4], al[4];
                uint32_t row = (uint32_t)(wm + mi * 16 + (lane & 15));
                uint32_t off = row * 64 + (uint32_t)(ks * 32) + ((lane >> 4) << 4);
                off ^= ((row >> 1) & 3) << 4;
                ldsm4(ah, sb + off);
                ldsm4(al, sb + 8192 + off);
#pragma unroll
                for (int ni = 0; ni < 4; ni++) {
                    const uint32_t* fh = &bh[(ni >> 1) * 4 + (ni & 1) * 2];
                    const uint32_t* fl = &bl[(ni >> 1) * 4 + (ni & 1) * 2];
                    float* d = acc[mi * 4 + ni];
                    mma16816(d, ah, fh);
                    mma16816(d, ah, fl);
                    mma16816(d, al, fh);
                }
            }
        }
    }

    // ---- epilogue: bias + store fp32
#pragma unroll
    for (int mi = 0; mi < 2; mi++) {
        int o0 = wm + mi * 16 + (lane >> 2);
        float bv0 = bias[o0], bv1 = bias[o0 + 8];
#pragma unroll
        for (int ni = 0; ni < 4; ni++) {
            int col = n0 + wn + ni * 8 + (lane & 3) * 2;
            const float* d = acc[mi * 4 + ni];
            float2 v0 = make_float2(d[0] + bv0, d[1] + bv0);
            float2 v1 = make_float2(d[2] + bv1, d[3] + bv1);
            *reinterpret_cast<float2*>(C + (size_t)o0 * Nn + col) = v0;
            *reinterpret_cast<float2*>(C + (size_t)(o0 + 8) * Nn + col) = v1;
        }
    }
}

// ---------------- weight pre-split -------------------------------------------
__global__ void k_prep(const float* __restrict__ g_w, const float* __restrict__ phi_w,
                       const float* __restrict__ W_w) {
    int i = blockIdx.x * 256 + threadIdx.x;   // < 32768
    float v = g_w[i];
    __nv_bfloat16 h = __float2bfloat16(v);
    d_wgh[i] = h; d_wgl[i] = __float2bfloat16(v - __bfloat162float(h));
    v = phi_w[i]; h = __float2bfloat16(v);
    d_wph[i] = h; d_wpl[i] = __float2bfloat16(v - __bfloat162float(h));
    v = W_w[i]; h = __float2bfloat16(v);
    d_wWh[i] = h; d_wWl[i] = __float2bfloat16(v - __bfloat162float(h));
}

// GEMM1: d_gp[b][which*128+o][n] = (g_w|phi_w)[o,:]·x[b,:,n] + bias[o]; K=256
__global__ __launch_bounds__(512) void k_mma1(const float* __restrict__ g_b,
                                              const float* __restrict__ phi_b) {
    extern __shared__ char sm[];
    int which = blockIdx.y, b = blockIdx.z;
    gemm_core<8>(which ? d_wph : d_wgh, which ? d_wpl : d_wgl, Cc,
                 which ? phi_b : g_b,
                 d_xh + (size_t)b * Cc * Nn, d_xl + (size_t)b * Cc * Nn,
                 d_gp + (size_t)(b * 2 + which) * ICc * Nn,
                 blockIdx.x * 128, sm);
}

// GEMM2: d_wy[b][by*128+c][n] = W_w[by*128+c,:]·yT[b,:,n] + W_b; K=128
__global__ __launch_bounds__(512) void k_mma2(const float* __restrict__ W_b) {
    extern __shared__ char sm[];
    int by = blockIdx.y, b = blockIdx.z;
    gemm_core<4>(d_wWh + (size_t)by * 128 * ICc, d_wWl + (size_t)by * 128 * ICc, ICc,
                 W_b + by * 128,
                 d_yh + (size_t)b * ICc * Nn, d_yl + (size_t)b * ICc * Nn,
                 d_wy + (size_t)(b * Cc + by * 128) * Nn,
                 blockIdx.x * 128, sm);
}

// ---------------- k_alpha: alpha = theta_w^T w_t ; bias_t = w_t . theta_b ----
__global__ void k_alpha(const float* __restrict__ theta_w,
                        const float* __restrict__ theta_b,
                        const float* __restrict__ cp_w) {
    int c = threadIdx.x;
    float a = 0.f;
    for (int ic = 0; ic < ICc; ic++) a += cp_w[ic] * theta_w[ic * Cc + c];
    d_alpha[c] = a;
    __shared__ float red[256];
    red[c] = (c < ICc) ? cp_w[c] * theta_b[c] : 0.f;
    __syncthreads();
    for (int s = 128; s > 0; s >>= 1) {
        if (c < s) red[c] += red[c + s];
        __syncthreads();
    }
    if (c == 0) d_bias_t[0] = red[0];
}

// ---------------- k_st: s_t = alpha·x[:,n] + bias_t; also splits x -> bf16 ---
__global__ __launch_bounds__(256) void k_st(const float* __restrict__ x) {
    __shared__ float part[8][33];
    int lane = threadIdx.x & 31, grp = threadIdx.x >> 5;
    int b = blockIdx.y, n = blockIdx.x * 32 + lane;
    const float* xb = x + (size_t)b * Cc * Nn + n;
    __nv_bfloat16* xh = d_xh + (size_t)b * Cc * Nn + n;
    __nv_bfloat16* xl = d_xl + (size_t)b * Cc * Nn + n;
    float s = 0.f;
#pragma unroll
    for (int j = 0; j < 32; j++) {
        int c = grp * 32 + j;
        float v = xb[(size_t)c * Nn];
        s = fmaf(d_alpha[c], v, s);
        __nv_bfloat16 h = __float2bfloat16(v);
        xh[(size_t)c * Nn] = h;
        xl[(size_t)c * Nn] = __float2bfloat16(v - __bfloat162float(h));
    }
    part[grp][lane] = s;
    __syncthreads();
    if (grp == 0) {
        float acc = d_bias_t[0];
#pragma unroll
        for (int g = 0; g < 8; g++) acc += part[g][lane];
        d_st[b * Nn + n] = acc;
    }
}

// ---------------- pooling + transpose (g and phi) ----------------------------
__global__ void k_pool() {
    __shared__ float tile[32][33];
    int b = blockIdx.z;
    int ic0 = blockIdx.y * 32, m0 = blockIdx.x * 32;
    int tx = threadIdx.x, ty = threadIdx.y;
    int m = m0 + tx;
    int ph = m >> 5, pw = m & 31;
    size_t nb = (size_t)ph * 128 + pw * 2;

    {
        const float* base = d_gp + ((size_t)b * 2 * ICc + (ic0 + ty)) * Nn + nb;
        float v = fmaxf(fmaxf(base[0], base[1]), fmaxf(base[64], base[65]));
        tile[ty][tx] = v;
        __syncthreads();
        d_gT[((size_t)b * Mm + (m0 + ty)) * ICc + ic0 + tx] = tile[tx][ty];
        __syncthreads();
    }
    {
        const float* base = d_gp + ((size_t)b * 2 * ICc + ICc + (ic0 + ty)) * Nn + nb;
        float v = fmaxf(fmaxf(base[0], base[1]), fmaxf(base[64], base[65]));
        tile[ty][tx] = v;
        __syncthreads();
        d_phiT[((size_t)b * Mm + (m0 + ty)) * ICc + ic0 + tx] = tile[tx][ty];
    }
}

// ---------------- s_p[b][m] = w_p . phi_pool[b,:,m] --------------------------
__global__ void k_sp(const float* __restrict__ cp_w) {
    int gw = blockIdx.x * 8 + (threadIdx.x >> 5);
    int lane = threadIdx.x & 31;
    int b = gw >> 10, m = gw & 1023;
    const float* p = d_phiT + ((size_t)b * Mm + m) * ICc;
    const float* wp = cp_w + ICc;
    float s = p[lane] * wp[lane] + p[lane + 32] * wp[lane + 32] +
              p[lane + 64] * wp[lane + 64] + p[lane + 96] * wp[lane + 96];
#pragma unroll
    for (int off = 16; off > 0; off >>= 1) s += __shfl_xor_sync(0xffffffffu, s, off);
    if (lane == 0) d_sp[b * Mm + m] = s;
}

// ---------------- bitonic sort of s_p per batch, descending ------------------
__global__ void k_sort() {
    __shared__ float key[1024];
    __shared__ int   idx[1024];
    int tid = threadIdx.x, b = blockIdx.x;
    key[tid] = d_sp[b * Mm + tid];
    idx[tid] = tid;
    __syncthreads();
    for (int k = 2; k <= 1024; k <<= 1) {
        for (int j = k >> 1; j > 0; j >>= 1) {
            int ixj = tid ^ j;
            if (ixj > tid) {
                bool up = ((tid & k) == 0);
                float a = key[tid], c = key[ixj];
                bool sw = up ? (a < c) : (a > c);
                if (sw) {
                    key[tid] = c; key[ixj] = a;
                    int t = idx[tid]; idx[tid] = idx[ixj]; idx[ixj] = t;
                }
            }
            __syncthreads();
        }
    }
    d_ss[b * Mm + tid] = key[tid];
    d_perm[b * Mm + tid] = idx[tid];
}

// ---------------- prefix tables over sorted order ----------------------------
__global__ void k_p1() {
    __shared__ int   sperm[128];
    __shared__ float sval[128];
    int b = blockIdx.y, ch = blockIdx.x, ic = threadIdx.x;
    sperm[ic] = d_perm[b * Mm + ch * 128 + ic];
    sval[ic]  = d_ss[b * Mm + ch * 128 + ic];
    __syncthreads();
    float s1 = 0.f, s2 = 0.f;
#pragma unroll 4
    for (int j = 0; j < 128; j++) {
        float g = d_gT[((size_t)b * Mm + sperm[j]) * ICc + ic];
        s1 += g;
        s2 = fmaf(sval[j], g, s2);
    }
    d_cs1[((size_t)b * 8 + ch) * ICc + ic] = s1;
    d_cs2[((size_t)b * 8 + ch) * ICc + ic] = s2;
}

__global__ void k_p2() {
    __shared__ int   sperm[128];
    __shared__ float sval[128];
    int b = blockIdx.y, ch = blockIdx.x, ic = threadIdx.x;
    sperm[ic] = d_perm[b * Mm + ch * 128 + ic];
    sval[ic]  = d_ss[b * Mm + ch * 128 + ic];
    __syncthreads();
    float r1 = 0.f, r2 = 0.f;
    for (int cc = 0; cc < ch; cc++) {
        r1 += d_cs1[((size_t)b * 8 + cc) * ICc + ic];
        r2 += d_cs2[((size_t)b * 8 + cc) * ICc + ic];
    }
#pragma unroll 4
    for (int j = 0; j < 128; j++) {
        int kg = ch * 128 + j;
        d_G1[((size_t)b * 1025 + kg) * ICc + ic] = r1;
        d_G2[((size_t)b * 1025 + kg) * ICc + ic] = r2;
        float g = d_gT[((size_t)b * Mm + sperm[j]) * ICc + ic];
        r1 += g;
        r2 = fmaf(sval[j], g, r2);
    }
    if (ch == 7) {
        d_G1[((size_t)b * 1025 + 1024) * ICc + ic] = r1;
        d_G2[((size_t)b * 1025 + 1024) * ICc + ic] = r2;
    }
}

// ---------------- y: yT[b][ic][n] (split bf16) -------------------------------
__global__ __launch_bounds__(256) void k_y() {
    extern __shared__ float tile[];          // [128][129]
    __shared__ int   s_lo[128];
    __shared__ float s_st[128];
    int t = threadIdx.x;
    int b = blockIdx.y, n0 = blockIdx.x * 128;

    if (t < 128) {
        float st = d_st[b * Nn + n0 + t];
        float tgt = -st;
        const float* ss = d_ss + b * Mm;
        int lo = 0, hi = 1024;
        while (lo < hi) {
            int mid = (lo + hi) >> 1;
            if (ss[mid] > tgt) lo = mid + 1; else hi = mid;
        }
        s_lo[t] = lo;
        s_st[t] = st;
    }
    __syncthreads();

    int ic = t & 127, nh = t >> 7;
    for (int j = 0; j < 64; j++) {
        int nl = nh * 64 + j;
        int lo = s_lo[nl];
        float st = s_st[nl];
        size_t gidx = ((size_t)b * 1025 + lo) * ICc + ic;
        tile[nl * 129 + ic] = (st * d_G1[gidx] + d_G2[gidx]) * (1.0f / 1024.0f);
    }
    __syncthreads();

    int nl = t & 127, half = t >> 7;
    for (int j = 0; j < 64; j++) {
        int ico = half * 64 + j;
        float v = tile[nl * 129 + ico];
        __nv_bfloat16 h = __float2bfloat16(v);
        size_t idx = ((size_t)b * ICc + ico) * Nn + n0 + nl;
        d_yh[idx] = h;
        d_yl[idx] = __float2bfloat16(v - __bfloat162float(h));
    }
}

// ---------------- BN stats per channel --------------------------------------
__global__ void k_bn(const float* __restrict__ gamma, const float* __restrict__ beta) {
    int c = blockIdx.x, tid = threadIdx.x;
    float s = 0.f, s2 = 0.f;
    for (int b = 0; b < Bn; b++) {
        const float* p = d_wy + ((size_t)b * Cc + c) * Nn;
        for (int n = tid; n < Nn; n += 256) {
            float v = p[n];
            s += v;
            s2 = fmaf(v, v, s2);
        }
    }
    __shared__ float r1[256], r2[256];
    r1[tid] = s; r2[tid] = s2;
    __syncthreads();
    for (int st = 128; st > 0; st >>= 1) {
        if (tid < st) { r1[tid] += r1[tid + st]; r2[tid] += r2[tid + st]; }
        __syncthreads();
    }
    if (tid == 0) {
        const float inv_cnt = 1.0f / (Bn * Nn);
        float mean = r1[0] * inv_cnt;
        float var = r2[0] * inv_cnt - mean * mean;
        float scale = rsqrtf(var + BN_EPS) * gamma[c];
        d_scale[c] = scale;
        d_shift[c] = beta[c] - mean * scale;
    }
}

// ---------------- final: out = wy*scale + shift + x --------------------------
__global__ void k_final(const float* __restrict__ x, float* __restrict__ out) {
    size_t i = ((size_t)blockIdx.x * 256 + threadIdx.x) * 4;
    int c = (int)((i / Nn) % Cc);
    float4 wv = *reinterpret_cast<const float4*>(d_wy + i);
    float4 xv = *reinterpret_cast<const float4*>(x + i);
    float sc = d_scale[c], sh = d_shift[c];
    float4 o;
    o.x = fmaf(wv.x, sc, sh) + xv.x;
    o.y = fmaf(wv.y, sc, sh) + xv.y;
    o.z = fmaf(wv.z, sc, sh) + xv.z;
    o.w = fmaf(wv.w, sc, sh) + xv.w;
    *reinterpret_cast<float4*>(out + i) = o;
}

// ---------------- launch -----------------------------------------------------
extern "C" void kernel_launch(void* const* d_in, const int* in_sizes, int n_in,
                              void* d_out, int out_size) {
    const float* x       = (const float*)d_in[0];
    const float* g_w     = (const float*)d_in[1];
    const float* g_b     = (const float*)d_in[2];
    const float* theta_w = (const float*)d_in[3];
    const float* theta_b = (const float*)d_in[4];
    const float* phi_w   = (const float*)d_in[5];
    const float* phi_b   = (const float*)d_in[6];
    const float* cp_w    = (const float*)d_in[7];
    const float* W_w     = (const float*)d_in[8];
    const float* W_b     = (const float*)d_in[9];
    const float* bn_g    = (const float*)d_in[10];
    const float* bn_b    = (const float*)d_in[11];
    float* out = (float*)d_out;

    static bool attr_done = false;
    if (!attr_done) {
        cudaFuncSetAttribute(k_mma1, cudaFuncAttributeMaxDynamicSharedMemorySize, GEMM_SMEM);
        cudaFuncSetAttribute(k_mma2, cudaFuncAttributeMaxDynamicSharedMemorySize, GEMM_SMEM);
        cudaFuncSetAttribute(k_y, cudaFuncAttributeMaxDynamicSharedMemorySize, 128 * 129 * 4);
        attr_done = true;
    }

    k_alpha<<<1, 256>>>(theta_w, theta_b, cp_w);
    k_prep<<<128, 256>>>(g_w, phi_w, W_w);
    k_st<<<dim3(Nn / 32, Bn), 256>>>(x);
    k_mma1<<<dim3(32, 2, Bn), 512, GEMM_SMEM>>>(g_b, phi_b);
    k_pool<<<dim3(32, 4, Bn), dim3(32, 32)>>>();
    k_sp<<<(Bn * Mm) / 8, 256>>>(cp_w);
    k_sort<<<Bn, 1024>>>();
    k_p1<<<dim3(8, Bn), 128>>>();
    k_p2<<<dim3(8, Bn), 128>>>();
    k_y<<<dim3(32, Bn), 256, 128 * 129 * 4>>>();
    k_mma2<<<dim3(32, 2, Bn), 512, GEMM_SMEM>>>(W_b);
    k_bn<<<Cc, 256>>>(bn_g, bn_b);
    k_final<<<(Bn * Cc * Nn) / (256 * 4), 256>>>(x, out);
}